// round 13
// baseline (speedup 1.0000x reference)
#include <cuda_runtime.h>
#include <cuda_fp16.h>

// Problem constants
#define BB 16
#define NN 4096
#define DD 6
#define SS 1024          // NUM_CENTERS
#define KK 32
#define ROWS (BB*SS*KK)  // 524288
#define NB2  4096        // layer12 blocks (128 rows each)
#define NCTR (BB*SS)     // 16384 centers
#define KNN_BPB 32
#define GSB 512          // gstats blocks

// ---------------- device scratch ----------------
__device__ int   g_gidx[ROWS];                       // 2 MB
__device__ __half2 g_x2h[(size_t)ROWS*32];           // 64 MB (fp16 x2)
__device__ float g_gstat[GSB*64];
__device__ float g_part2[NB2*128];
__device__ float g_p2b[32*128];
__device__ float g_part3[(size_t)NCTR*256];
__device__ float g_p3b[128*256];
__device__ float g_max3[(size_t)NCTR*128];
__device__ float g_min3[(size_t)NCTR*128];
__device__ float g_s1[64], g_b1o[64], g_s2[64], g_b2o[64], g_s3[128], g_b3o[128];
__device__ unsigned g_ctr1, g_ctr2, g_ctr3;

// packed f32x2 helpers
__device__ __forceinline__ unsigned long long pack2(float lo, float hi){
    unsigned long long r;
    asm("mov.b64 %0, {%1, %2};" : "=l"(r) : "f"(lo), "f"(hi));
    return r;
}
__device__ __forceinline__ void unpack2(unsigned long long v, float& lo, float& hi){
    asm("mov.b64 {%0, %1}, %2;" : "=f"(lo), "=f"(hi) : "l"(v));
}
__device__ __forceinline__ unsigned long long add2(unsigned long long a, unsigned long long b){
    unsigned long long r; asm("add.rn.f32x2 %0, %1, %2;" : "=l"(r) : "l"(a), "l"(b)); return r;
}
__device__ __forceinline__ unsigned long long mul2(unsigned long long a, unsigned long long b){
    unsigned long long r; asm("mul.rn.f32x2 %0, %1, %2;" : "=l"(r) : "l"(a), "l"(b)); return r;
}

// mma helpers
__device__ __forceinline__ unsigned smem_u32(const void* p){
    return (unsigned)__cvta_generic_to_shared(p);
}
__device__ __forceinline__ void ldmA(unsigned* r, unsigned addr){
    asm volatile("ldmatrix.sync.aligned.m8n8.x4.shared.b16 {%0,%1,%2,%3}, [%4];"
        : "=r"(r[0]),"=r"(r[1]),"=r"(r[2]),"=r"(r[3]) : "r"(addr));
}
__device__ __forceinline__ void ldmB(unsigned& b0, unsigned& b1, unsigned addr){
    asm volatile("ldmatrix.sync.aligned.m8n8.x2.trans.shared.b16 {%0,%1}, [%2];"
        : "=r"(b0),"=r"(b1) : "r"(addr));
}
__device__ __forceinline__ void mma16816(float* d, const unsigned* a, const unsigned* b){
    asm volatile("mma.sync.aligned.m16n8k16.row.col.f32.f16.f16.f32 "
        "{%0,%1,%2,%3}, {%4,%5,%6,%7}, {%8,%9}, {%0,%1,%2,%3};"
        : "+f"(d[0]),"+f"(d[1]),"+f"(d[2]),"+f"(d[3])
        : "r"(a[0]),"r"(a[1]),"r"(a[2]),"r"(a[3]), "r"(b[0]),"r"(b[1]));
}

// =========================================================================
// FPS v7: 1024 thr x 4 pts. Value-only FMNMX max + first-occurrence index
// recovery (same tie policy, ~6 fewer instrs/iter on the issue-bound path).
// =========================================================================
__global__ void __launch_bounds__(1024) fps_kernel(const float* __restrict__ xyz,
                                                   float* __restrict__ out_cxyz)
{
    extern __shared__ float fsm[];
    float* sxx = fsm; float* syy = fsm + NN; float* szz = fsm + 2*NN;
    __shared__ unsigned swd[2][32];
    __shared__ unsigned swi[2][32];

    const int b   = blockIdx.x;
    const int tid = threadIdx.x;
    const float* bx = xyz + (size_t)b * NN * 3;

    for (int idx = tid; idx < NN; idx += 1024) {
        sxx[idx] = bx[idx*3+0]; syy[idx] = bx[idx*3+1]; szz[idx] = bx[idx*3+2];
    }
    __syncthreads();

    unsigned long long pxp[2], pyp[2], pzp[2];
    #pragma unroll
    for (int j = 0; j < 2; j++) {
        int p0 = tid*4 + 2*j;
        pxp[j] = pack2(sxx[p0], sxx[p0+1]);
        pyp[j] = pack2(syy[p0], syy[p0+1]);
        pzp[j] = pack2(szz[p0], szz[p0+1]);
    }
    float dmin[4];
    float c0x = sxx[0], c0y = syy[0], c0z = szz[0];
    {
        unsigned long long ncx = pack2(-c0x, -c0x);
        unsigned long long ncy = pack2(-c0y, -c0y);
        unsigned long long ncz = pack2(-c0z, -c0z);
        #pragma unroll
        for (int j = 0; j < 2; j++) {
            unsigned long long dx = add2(pxp[j], ncx);
            unsigned long long dy = add2(pyp[j], ncy);
            unsigned long long dz = add2(pzp[j], ncz);
            unsigned long long s = add2(add2(mul2(dx,dx), mul2(dy,dy)), mul2(dz,dz));
            unpack2(s, dmin[2*j], dmin[2*j+1]);
        }
    }
    if (tid == 0) {
        out_cxyz[(size_t)b*SS*3+0] = c0x;
        out_cxyz[(size_t)b*SS*3+1] = c0y;
        out_cxyz[(size_t)b*SS*3+2] = c0z;
    }

    const int lane = tid & 31, warp = tid >> 5;
    const unsigned full = 0xFFFFFFFFu;

    // local argmax: value max + first-occurrence index recovery
    float db; int bi_;
    {
        float m = fmaxf(fmaxf(dmin[0], dmin[1]), fmaxf(dmin[2], dmin[3]));
        int li = (dmin[0] == m) ? 0 : (dmin[1] == m) ? 1 : (dmin[2] == m) ? 2 : 3;
        db = m; bi_ = tid*4 + li;
    }

    for (int t = 1; t < SS; t++) {
        unsigned dmax = __reduce_max_sync(full, __float_as_uint(db));
        unsigned cand = (__float_as_uint(db) == dmax) ? (unsigned)bi_ : 0xFFFFFFFFu;
        unsigned imin = __reduce_min_sync(full, cand);
        if (lane == 0) { swd[t&1][warp] = dmax; swi[t&1][warp] = imin; }
        __syncthreads();

        unsigned wd = swd[t&1][lane];
        unsigned wi = swi[t&1][lane];
        unsigned gmax  = __reduce_max_sync(full, wd);
        unsigned gcand = (wd == gmax) ? wi : 0xFFFFFFFFu;
        int idx = (int)__reduce_min_sync(full, gcand);

        float cx = sxx[idx], cy = syy[idx], cz = szz[idx];
        if (tid == 0) {
            out_cxyz[((size_t)b*SS + t)*3+0] = cx;
            out_cxyz[((size_t)b*SS + t)*3+1] = cy;
            out_cxyz[((size_t)b*SS + t)*3+2] = cz;
        }
        unsigned long long ncx = pack2(-cx, -cx);
        unsigned long long ncy = pack2(-cy, -cy);
        unsigned long long ncz = pack2(-cz, -cz);
        #pragma unroll
        for (int j = 0; j < 2; j++) {
            unsigned long long dx = add2(pxp[j], ncx);
            unsigned long long dy = add2(pyp[j], ncy);
            unsigned long long dz = add2(pzp[j], ncz);
            unsigned long long s = add2(add2(mul2(dx,dx), mul2(dy,dy)), mul2(dz,dz));
            float lo, hi; unpack2(s, lo, hi);
            dmin[2*j]   = fminf(dmin[2*j],   lo);
            dmin[2*j+1] = fminf(dmin[2*j+1], hi);
        }
        float m = fmaxf(fmaxf(dmin[0], dmin[1]), fmaxf(dmin[2], dmin[3]));
        int li = (dmin[0] == m) ? 0 : (dmin[1] == m) ? 1 : (dmin[2] == m) ? 2 : 3;
        db = m; bi_ = tid*4 + li;
    }
}

// =========================================================================
// kNN: 4 centers per streaming pass, pair-threshold eviction (bit-identical
// selection policy to reference top_k). 48KB static staging.
// =========================================================================
__global__ void __launch_bounds__(256) knn_kernel(const float* __restrict__ xyz,
                                                  const float* __restrict__ cxyz)
{
    __shared__ float sx[NN], sy[NN], sz[NN];
    const int b     = blockIdx.x >> 5;
    const int blkin = blockIdx.x & 31;
    const int tid   = threadIdx.x;
    const float* bx = xyz + (size_t)b * NN * 3;

    for (int j = tid; j < NN; j += 256) {
        sx[j] = bx[j*3+0]; sy[j] = bx[j*3+1]; sz[j] = bx[j*3+2];
    }
    __syncthreads();

    const int warp = tid >> 5, lane = tid & 31;
    const unsigned full = 0xFFFFFFFFu;
    const int sbase = (blkin * 8 + warp) * 4;

    float ax[4], ay[4], az[4], ra[4];
    #pragma unroll
    for (int m = 0; m < 4; m++) {
        ax[m] = cxyz[((size_t)b*SS + sbase + m)*3+0];
        ay[m] = cxyz[((size_t)b*SS + sbase + m)*3+1];
        az[m] = cxyz[((size_t)b*SS + sbase + m)*3+2];
        ra[m] = __fadd_rn(__fadd_rn(__fmul_rn(ax[m],ax[m]), __fmul_rn(ay[m],ay[m])),
                          __fmul_rn(az[m],az[m]));
    }

    unsigned hdu[4]; int hi[4]; unsigned thr_d[4]; int thr_i[4];
    {
        float bxx = sx[lane], byy = sy[lane], bzz = sz[lane];
        float rb  = __fadd_rn(__fadd_rn(__fmul_rn(bxx,bxx), __fmul_rn(byy,byy)), __fmul_rn(bzz,bzz));
        #pragma unroll
        for (int m = 0; m < 4; m++) {
            float dot = __fadd_rn(__fadd_rn(__fmul_rn(ax[m],bxx), __fmul_rn(ay[m],byy)), __fmul_rn(az[m],bzz));
            float d = fmaxf(__fsub_rn(__fadd_rn(ra[m], rb), __fmul_rn(2.0f, dot)), 0.0f);
            hdu[m] = __float_as_uint(d);
            hi[m] = lane;
            thr_d[m] = __reduce_max_sync(full, hdu[m]);
            thr_i[m] = __reduce_max_sync(full, (hdu[m] == thr_d[m]) ? hi[m] : -1);
        }
    }

    for (int j0 = 32; j0 < NN; j0 += 32) {
        int j = j0 + lane;
        float bxx = sx[j], byy = sy[j], bzz = sz[j];
        float rb  = __fadd_rn(__fadd_rn(__fmul_rn(bxx,bxx), __fmul_rn(byy,byy)), __fmul_rn(bzz,bzz));
        unsigned du[4];
        #pragma unroll
        for (int m = 0; m < 4; m++) {
            float dot = __fadd_rn(__fadd_rn(__fmul_rn(ax[m],bxx), __fmul_rn(ay[m],byy)), __fmul_rn(az[m],bzz));
            float d = fmaxf(__fsub_rn(__fadd_rn(ra[m], rb), __fmul_rn(2.0f, dot)), 0.0f);
            du[m] = __float_as_uint(d);
        }
        #pragma unroll
        for (int m = 0; m < 4; m++) {
            unsigned cm = __ballot_sync(full, du[m] < thr_d[m]);
            while (cm) {
                int src = __ffs(cm) - 1;
                cm &= cm - 1;
                unsigned cd = __shfl_sync(full, du[m], src);
                int ci = j0 + src;
                if (cd < thr_d[m]) {
                    if (hdu[m] == thr_d[m] && hi[m] == thr_i[m]) { hdu[m] = cd; hi[m] = ci; }
                    thr_d[m] = __reduce_max_sync(full, hdu[m]);
                    thr_i[m] = __reduce_max_sync(full, (hdu[m] == thr_d[m]) ? hi[m] : -1);
                }
            }
        }
    }
    #pragma unroll
    for (int m = 0; m < 4; m++)
        g_gidx[((size_t)b*SS + sbase + m)*KK + lane] = hi[m];
}

// =========================================================================
// G stats + fused BN1 solve (last block via counter; deterministic).
// =========================================================================
__global__ void __launch_bounds__(256) gstats_kernel(const float* __restrict__ xyz,
                                                     const float* __restrict__ feat,
                                                     const float* __restrict__ cxyz,
                                                     const float* __restrict__ W1,
                                                     const float* __restrict__ g1v,
                                                     const float* __restrict__ b1v)
{
    const int tid = threadIdx.x;
    const int t0  = blockIdx.x * 1024 + tid;
    float s[9]; float m2[45];
    #pragma unroll
    for (int i = 0; i < 9; i++) s[i] = 0.f;
    #pragma unroll
    for (int i = 0; i < 45; i++) m2[i] = 0.f;

    #pragma unroll
    for (int m = 0; m < 4; m++) {
        int r = t0 + m*256;
        int bb = r >> 15, ssi = (r >> 5) & (SS-1);
        int gi = __ldg(&g_gidx[r]);
        const float* c = cxyz + ((size_t)bb*SS + ssi)*3;
        const float* p = xyz  + ((size_t)bb*NN + gi)*3;
        const float2* f2 = (const float2*)(feat + ((size_t)bb*NN + gi)*DD);
        float g[9];
        g[0] = __ldg(&p[0]) - __ldg(&c[0]);
        g[1] = __ldg(&p[1]) - __ldg(&c[1]);
        g[2] = __ldg(&p[2]) - __ldg(&c[2]);
        float2 fa = __ldg(&f2[0]), fb = __ldg(&f2[1]), fc = __ldg(&f2[2]);
        g[3] = fa.x; g[4] = fa.y; g[5] = fb.x; g[6] = fb.y; g[7] = fc.x; g[8] = fc.y;
        #pragma unroll
        for (int i = 0; i < 9; i++) s[i] += g[i];
        int k = 0;
        #pragma unroll
        for (int i = 0; i < 9; i++)
            #pragma unroll
            for (int j = i; j < 9; j++) { m2[k] = fmaf(g[i], g[j], m2[k]); k++; }
    }
    const unsigned full = 0xFFFFFFFFu;
    #pragma unroll
    for (int q = 0; q < 9; q++)
        for (int o = 16; o > 0; o >>= 1) s[q] += __shfl_xor_sync(full, s[q], o);
    #pragma unroll
    for (int q = 0; q < 45; q++)
        for (int o = 16; o > 0; o >>= 1) m2[q] += __shfl_xor_sync(full, m2[q], o);

    __shared__ float sred[8][56];
    const int lane = tid & 31, warp = tid >> 5;
    if (lane == 0) {
        #pragma unroll
        for (int q = 0; q < 9; q++)  sred[warp][q]   = s[q];
        #pragma unroll
        for (int q = 0; q < 45; q++) sred[warp][9+q] = m2[q];
    }
    __syncthreads();
    if (tid < 54) {
        float a = 0.f;
        #pragma unroll
        for (int w = 0; w < 8; w++) a += sred[w][tid];
        g_gstat[blockIdx.x*64 + tid] = a;
    }

    __shared__ unsigned is_last;
    __threadfence();
    if (tid == 0) is_last = (atomicAdd(&g_ctr1, 1u) == GSB - 1);
    __syncthreads();
    if (!is_last) return;

    __shared__ float part[4][64];
    __shared__ double st[54];
    {
        const int c = tid & 63, r4 = tid >> 6;
        float a0 = 0.f, a1 = 0.f;
        for (int p = r4; p < GSB; p += 8) {
            a0 += g_gstat[p*64 + c];
            a1 += g_gstat[(p+4)*64 + c];
        }
        part[r4][c] = a0 + a1;
    }
    __syncthreads();
    if (tid < 54) st[tid] = (double)(part[0][tid] + part[1][tid] + part[2][tid] + part[3][tid]);
    __syncthreads();
    if (tid < 64) {
        const int t = tid;
        const double Ri = 1.0 / 524288.0;
        double w[9];
        #pragma unroll
        for (int i = 0; i < 9; i++) w[i] = (double)__ldg(&W1[i*64 + t]);
        double m1 = 0.0;
        #pragma unroll
        for (int i = 0; i < 9; i++) m1 += st[i]*Ri*w[i];
        double e2 = 0.0; int k = 0;
        #pragma unroll
        for (int i = 0; i < 9; i++)
            #pragma unroll
            for (int j = i; j < 9; j++) {
                double term = st[9+k]*Ri*w[i]*w[j];
                e2 += (i == j) ? term : 2.0*term;
                k++;
            }
        double var = e2 - m1*m1;
        double sc = (double)__ldg(&g1v[t]) / sqrt(var + 1e-5);
        g_s1[t]  = (float)sc;
        g_b1o[t] = (float)((double)__ldg(&b1v[t]) - m1*sc);
    }
    if (tid == 0) g_ctr1 = 0u;
}

// =========================================================================
// Fused layer1+2 via mma.sync fp16 (stats inline, coalesced x2 stores).
// =========================================================================
__global__ void __launch_bounds__(256) layer12_mma(const float* __restrict__ xyz,
                                                   const float* __restrict__ feat,
                                                   const float* __restrict__ cxyz,
                                                   const float* __restrict__ W1,
                                                   const float* __restrict__ W2)
{
    __shared__ __half w2h[64*72];
    __shared__ __half h1s[128*72];
    __shared__ float sg[128*10];
    __shared__ float rs[8][64], rq[8][64];

    const int tid = threadIdx.x;
    const int rowbase = blockIdx.x * 128;
    const int warp = tid >> 5, lane = tid & 31;
    const unsigned full = 0xFFFFFFFFu;

    for (int i = tid; i < 4096; i += 256) {
        int k = i >> 6, n = i & 63;
        w2h[k*72 + n] = __float2half(__ldg(&W2[i]));
    }

    if (tid < 128) {
        int r = rowbase + tid;
        int bb = r >> 15, ssi = (r >> 5) & (SS-1);
        int gi = __ldg(&g_gidx[r]);
        const float* c = cxyz + ((size_t)bb*SS + ssi)*3;
        const float* p = xyz  + ((size_t)bb*NN + gi)*3;
        const float2* f2 = (const float2*)(feat + ((size_t)bb*NN + gi)*DD);
        float* gg = sg + tid*10;
        gg[0] = __ldg(&p[0]) - __ldg(&c[0]);
        gg[1] = __ldg(&p[1]) - __ldg(&c[1]);
        gg[2] = __ldg(&p[2]) - __ldg(&c[2]);
        float2 fa = __ldg(&f2[0]), fb = __ldg(&f2[1]), fc = __ldg(&f2[2]);
        gg[3] = fa.x; gg[4] = fa.y; gg[5] = fb.x; gg[6] = fb.y; gg[7] = fc.x; gg[8] = fc.y;
    }
    __syncthreads();

    {
        const int c2 = tid & 31, r0 = tid >> 5;
        float wa[9], wb[9];
        #pragma unroll
        for (int i = 0; i < 9; i++) {
            wa[i] = __ldg(&W1[i*64 + 2*c2]);
            wb[i] = __ldg(&W1[i*64 + 2*c2 + 1]);
        }
        const float sa = g_s1[2*c2], sb = g_s1[2*c2+1];
        const float ba = g_b1o[2*c2], bbv = g_b1o[2*c2+1];
        #pragma unroll 4
        for (int m = 0; m < 16; m++) {
            int row = r0 + 8*m;
            const float* gg = sg + row*10;
            float xa = gg[0]*wa[0], xb = gg[0]*wb[0];
            #pragma unroll
            for (int i = 1; i < 9; i++) { float gv = gg[i]; xa = fmaf(gv, wa[i], xa); xb = fmaf(gv, wb[i], xb); }
            float ha = fmaxf(fmaf(xa, sa, ba), 0.f);
            float hb = fmaxf(fmaf(xb, sb, bbv), 0.f);
            *(__half2*)&h1s[row*72 + 2*c2] = __floats2half2_rn(ha, hb);
        }
    }
    __syncthreads();

    unsigned af[4][4];
    #pragma unroll
    for (int kt = 0; kt < 4; kt++) {
        unsigned addr = smem_u32(&h1s[(warp*16 + (lane & 15))*72 + kt*16 + (lane >> 4)*8]);
        ldmA(af[kt], addr);
    }
    __syncthreads();

    #pragma unroll
    for (int nt = 0; nt < 8; nt++) {
        unsigned bf[4][2];
        #pragma unroll
        for (int kt = 0; kt < 4; kt++) {
            unsigned addr = smem_u32(&w2h[(kt*16 + (lane & 15))*72 + nt*8]);
            ldmB(bf[kt][0], bf[kt][1], addr);
        }
        float c[4] = {0.f, 0.f, 0.f, 0.f};
        #pragma unroll
        for (int kt = 0; kt < 4; kt++) mma16816(c, af[kt], bf[kt]);

        {
            int r0s = warp*16 + (lane >> 2);
            int h2c = nt*4 + (lane & 3);
            *(__half2*)&h1s[r0s*72 + 2*h2c]     = __floats2half2_rn(c[0], c[1]);
            *(__half2*)&h1s[(r0s+8)*72 + 2*h2c] = __floats2half2_rn(c[2], c[3]);
        }
        float s0 = c[0] + c[2], s1 = c[1] + c[3];
        float q0 = fmaf(c[0], c[0], c[2]*c[2]);
        float q1 = fmaf(c[1], c[1], c[3]*c[3]);
        #pragma unroll
        for (int o = 4; o < 32; o <<= 1) {
            s0 += __shfl_xor_sync(full, s0, o);
            s1 += __shfl_xor_sync(full, s1, o);
            q0 += __shfl_xor_sync(full, q0, o);
            q1 += __shfl_xor_sync(full, q1, o);
        }
        if (lane < 4) {
            int col = nt*8 + 2*lane;
            rs[warp][col]     = s0; rs[warp][col + 1] = s1;
            rq[warp][col]     = q0; rq[warp][col + 1] = q1;
        }
    }
    __syncthreads();

    {
        char* dst = (char*)(g_x2h + (size_t)rowbase*32);
        const char* srcs = (const char*)h1s;
        #pragma unroll
        for (int j = 0; j < 4; j++) {
            int o = tid*16 + j*4096;
            int row = o >> 7, colb = o & 127;
            uint4 v = *(const uint4*)(srcs + row*144 + colb);
            *(uint4*)(dst + o) = v;
        }
    }
    if (tid < 64) {
        float a = 0.f, qq = 0.f;
        #pragma unroll
        for (int w = 0; w < 8; w++) { a += rs[w][tid]; qq += rq[w][tid]; }
        g_part2[blockIdx.x*128 + tid]      = a;
        g_part2[blockIdx.x*128 + 64 + tid] = qq;
    }
}

// -------- BN2: merged two-stage reduction (last-block finalize) --------
__global__ void __launch_bounds__(256) bn2_kernel(const float* __restrict__ g,
                                                  const float* __restrict__ bv)
{
    const int tid = threadIdx.x;
    {
        const int h = tid >> 7, c = tid & 127;
        float a = 0.f;
        #pragma unroll 8
        for (int j = 0; j < 64; j++) {
            int p = blockIdx.x*128 + h + 2*j;
            a += g_part2[p*128 + c];
        }
        __shared__ float sm[256];
        sm[tid] = a;
        __syncthreads();
        if (tid < 128) g_p2b[blockIdx.x*128 + tid] = sm[tid] + sm[tid + 128];
    }
    __shared__ unsigned is_last;
    __threadfence();
    if (tid == 0) is_last = (atomicAdd(&g_ctr2, 1u) == 31);
    __syncthreads();
    if (!is_last) return;

    if (tid < 64) {
        float s = 0.f, q = 0.f;
        #pragma unroll 8
        for (int b = 0; b < 32; b++) {
            s += g_p2b[b*128 + tid];
            q += g_p2b[b*128 + 64 + tid];
        }
        float m = s * (1.0f/524288.0f);
        float v = q * (1.0f/524288.0f) - m*m;
        float sc = __ldg(&g[tid]) * rsqrtf(v + 1e-5f);
        g_s2[tid] = sc; g_b2o[tid] = __ldg(&bv[tid]) - m*sc;
    }
    if (tid == 0) g_ctr2 = 0u;
}

// =========================================================================
// Layer 3 via mma.sync fp16 tensor cores.
// =========================================================================
__global__ void __launch_bounds__(256) layer3_mma(const float* __restrict__ W3)
{
    __shared__ __half w3h[64*136];
    __shared__ __half h2s[2][32*72];
    __shared__ float s2s[64], b2s[64];

    const int tid = threadIdx.x;
    const int warp = tid >> 5, lane = tid & 31;
    const int sub = warp >> 2;
    const int wq  = warp & 3;
    const int n0  = wq * 32;
    const unsigned full = 0xFFFFFFFFu;

    for (int i = tid; i < 8192; i += 256) {
        int k = i >> 7, n = i & 127;
        w3h[k*136 + n] = __float2half(__ldg(&W3[i]));
    }
    if (tid < 64) { s2s[tid] = g_s2[tid]; b2s[tid] = g_b2o[tid]; }
    __syncthreads();

    unsigned bfrag[4][4][2];
    #pragma unroll
    for (int nt = 0; nt < 4; nt++)
        #pragma unroll
        for (int kt = 0; kt < 4; kt++) {
            unsigned addr = smem_u32(&w3h[(kt*16 + (lane & 15))*136 + n0 + nt*8]);
            ldmB(bfrag[nt][kt][0], bfrag[nt][kt][1], addr);
        }

    const int tid128 = tid & 127;
    const int kkrow  = tid128 >> 2;
    const int cg     = (tid128 & 3) * 8;

    for (int cc = 0; cc < 8; cc++) {
        const int bs = blockIdx.x*16 + cc*2 + sub;
        __syncthreads();

        {
            const __half2* src = &g_x2h[((size_t)bs*KK + kkrow)*32 + cg];
            uint4 v0 = *(const uint4*)(src);
            uint4 v1 = *(const uint4*)(src + 4);
            unsigned vv[8] = {v0.x, v0.y, v0.z, v0.w, v1.x, v1.y, v1.z, v1.w};
            #pragma unroll
            for (int j = 0; j < 8; j++) {
                __half2 hv = *(__half2*)&vv[j];
                float2 f = __half22float2(hv);
                int ch = 2*(cg + j);
                float ha = fmaxf(fmaf(f.x, s2s[ch],   b2s[ch]),   0.f);
                float hb = fmaxf(fmaf(f.y, s2s[ch+1], b2s[ch+1]), 0.f);
                *(__half2*)&h2s[sub][kkrow*72 + ch] = __floats2half2_rn(ha, hb);
            }
        }
        __syncthreads();

        unsigned af[2][4][4];
        #pragma unroll
        for (int mt = 0; mt < 2; mt++)
            #pragma unroll
            for (int kt = 0; kt < 4; kt++) {
                unsigned addr = smem_u32(&h2s[sub][(mt*16 + (lane & 15))*72
                                                   + kt*16 + (lane >> 4)*8]);
                ldmA(af[mt][kt], addr);
            }

        const size_t bs128 = (size_t)bs*128;
        const size_t bs256 = (size_t)bs*256;

        #pragma unroll
        for (int nt = 0; nt < 4; nt++) {
            float ac[2][4];
            #pragma unroll
            for (int mt = 0; mt < 2; mt++) {
                ac[mt][0] = 0.f; ac[mt][1] = 0.f; ac[mt][2] = 0.f; ac[mt][3] = 0.f;
                #pragma unroll
                for (int kt = 0; kt < 4; kt++)
                    mma16816(ac[mt], af[mt][kt], bfrag[nt][kt]);
            }
            float mx0 = fmaxf(fmaxf(ac[0][0], ac[0][2]), fmaxf(ac[1][0], ac[1][2]));
            float mx1 = fmaxf(fmaxf(ac[0][1], ac[0][3]), fmaxf(ac[1][1], ac[1][3]));
            float mn0 = fminf(fminf(ac[0][0], ac[0][2]), fminf(ac[1][0], ac[1][2]));
            float mn1 = fminf(fminf(ac[0][1], ac[0][3]), fminf(ac[1][1], ac[1][3]));
            float sm0 = (ac[0][0] + ac[0][2]) + (ac[1][0] + ac[1][2]);
            float sm1 = (ac[0][1] + ac[0][3]) + (ac[1][1] + ac[1][3]);
            float sq0 = fmaf(ac[0][0],ac[0][0], fmaf(ac[0][2],ac[0][2],
                        fmaf(ac[1][0],ac[1][0], ac[1][2]*ac[1][2])));
            float sq1 = fmaf(ac[0][1],ac[0][1], fmaf(ac[0][3],ac[0][3],
                        fmaf(ac[1][1],ac[1][1], ac[1][3]*ac[1][3])));
            #pragma unroll
            for (int o = 4; o < 32; o <<= 1) {
                mx0 = fmaxf(mx0, __shfl_xor_sync(full, mx0, o));
                mx1 = fmaxf(mx1, __shfl_xor_sync(full, mx1, o));
                mn0 = fminf(mn0, __shfl_xor_sync(full, mn0, o));
                mn1 = fminf(mn1, __shfl_xor_sync(full, mn1, o));
                sm0 += __shfl_xor_sync(full, sm0, o);
                sm1 += __shfl_xor_sync(full, sm1, o);
                sq0 += __shfl_xor_sync(full, sq0, o);
                sq1 += __shfl_xor_sync(full, sq1, o);
            }
            if (lane < 4) {
                int col = n0 + nt*8 + 2*lane;
                g_max3[bs128 + col]     = mx0;
                g_max3[bs128 + col + 1] = mx1;
                g_min3[bs128 + col]     = mn0;
                g_min3[bs128 + col + 1] = mn1;
                g_part3[bs256 + col]           = sm0;
                g_part3[bs256 + col + 1]       = sm1;
                g_part3[bs256 + 128 + col]     = sq0;
                g_part3[bs256 + 128 + col + 1] = sq1;
            }
        }
    }
}

// -------- BN3: merged two-stage reduction (last-block finalize) --------
__global__ void __launch_bounds__(256) bn3_kernel(const float* __restrict__ g,
                                                  const float* __restrict__ bv)
{
    const int tid = threadIdx.x;
    {
        float a = 0.f;
        #pragma unroll 8
        for (int p = 0; p < 128; p++)
            a += g_part3[((size_t)blockIdx.x*128 + p)*256 + tid];
        g_p3b[blockIdx.x*256 + tid] = a;
    }
    __shared__ unsigned is_last;
    __threadfence();
    if (tid == 0) is_last = (atomicAdd(&g_ctr3, 1u) == 127);
    __syncthreads();
    if (!is_last) return;

    {
        const int h = tid >> 7, c = tid & 127;
        float s = 0.f, q = 0.f;
        #pragma unroll 8
        for (int j = 0; j < 64; j++) {
            int b = h + 2*j;
            s += g_p3b[b*256 + c];
            q += g_p3b[b*256 + 128 + c];
        }
        __shared__ float ssm[256], qsm[256];
        ssm[tid] = s; qsm[tid] = q;
        __syncthreads();
        if (tid < 128) {
            float ts = ssm[tid] + ssm[tid + 128];
            float tq = qsm[tid] + qsm[tid + 128];
            float m = ts * (1.0f/524288.0f);
            float v = tq * (1.0f/524288.0f) - m*m;
            float sc = __ldg(&g[tid]) * rsqrtf(v + 1e-5f);
            g_s3[tid] = sc; g_b3o[tid] = __ldg(&bv[tid]) - m*sc;
        }
    }
    if (tid == 0) g_ctr3 = 0u;
}

// max_k relu(s*x+b) = relu(s*(s>=0? max:min) + b)
__global__ void final_kernel(float* __restrict__ out_feat)
{
    int idx = blockIdx.x * 256 + threadIdx.x;
    int c = idx & 127;
    float sc = g_s3[c], bi = g_b3o[c];
    float v = (sc >= 0.f) ? g_max3[idx] : g_min3[idx];
    out_feat[idx] = fmaxf(fmaf(v, sc, bi), 0.f);
}

// =========================================================================
extern "C" void kernel_launch(void* const* d_in, const int* in_sizes, int n_in,
                              void* d_out, int out_size)
{
    const float* xyz  = (const float*)d_in[0];
    const float* feat = (const float*)d_in[1];
    const float* W1   = (const float*)d_in[2];
    const float* g1   = (const float*)d_in[3];
    const float* b1   = (const float*)d_in[4];
    const float* W2   = (const float*)d_in[5];
    const float* g2   = (const float*)d_in[6];
    const float* b2   = (const float*)d_in[7];
    const float* W3   = (const float*)d_in[8];
    const float* g3   = (const float*)d_in[9];
    const float* b3   = (const float*)d_in[10];

    float* out   = (float*)d_out;
    float* cxyz  = out;                      // [16,1024,3]
    float* ofeat = out + (size_t)BB*SS*3;    // [16,1024,128]

    cudaFuncSetAttribute(fps_kernel, cudaFuncAttributeMaxDynamicSharedMemorySize, NN*3*4);

    fps_kernel    <<<BB, 1024, NN*3*4>>>(xyz, cxyz);
    knn_kernel    <<<BB*KNN_BPB, 256>>>(xyz, cxyz);
    gstats_kernel <<<GSB, 256>>>(xyz, feat, cxyz, W1, g1, b1);
    layer12_mma   <<<NB2, 256>>>(xyz, feat, cxyz, W1, W2);
    bn2_kernel    <<<32, 256>>>(g2, b2);
    layer3_mma    <<<NCTR/16, 256>>>(W3);
    bn3_kernel    <<<128, 256>>>(g3, b3);
    final_kernel  <<<(BB*SS*128)/256, 256>>>(ofeat);
}

// round 14
// speedup vs baseline: 1.0529x; 1.0529x over previous
#include <cuda_runtime.h>
#include <cuda_fp16.h>

// Problem constants
#define BB 16
#define NN 4096
#define DD 6
#define SS 1024          // NUM_CENTERS
#define KK 32
#define ROWS (BB*SS*KK)  // 524288
#define NB2  4096        // layer12 blocks (128 rows each)
#define NCTR (BB*SS)     // 16384 centers
#define KNN_BPB 32
#define GSB 512          // gstats blocks

// ---------------- device scratch ----------------
__device__ int   g_gidx[ROWS];                       // 2 MB
__device__ __half2 g_x2h[(size_t)ROWS*32];           // 64 MB (fp16 x2)
__device__ float g_gstat[GSB*64];
__device__ float g_part2[NB2*128];
__device__ float g_p2b[32*128];
__device__ float g_part3[(size_t)NCTR*256];
__device__ float g_p3b[128*256];
__device__ float g_max3[(size_t)NCTR*128];
__device__ float g_min3[(size_t)NCTR*128];
__device__ float g_s1[64], g_b1o[64], g_s2[64], g_b2o[64], g_s3[128], g_b3o[128];
__device__ unsigned g_ctr1, g_ctr2, g_ctr3;

// packed f32x2 helpers
__device__ __forceinline__ unsigned long long pack2(float lo, float hi){
    unsigned long long r;
    asm("mov.b64 %0, {%1, %2};" : "=l"(r) : "f"(lo), "f"(hi));
    return r;
}
__device__ __forceinline__ void unpack2(unsigned long long v, float& lo, float& hi){
    asm("mov.b64 {%0, %1}, %2;" : "=f"(lo), "=f"(hi) : "l"(v));
}
__device__ __forceinline__ unsigned long long add2(unsigned long long a, unsigned long long b){
    unsigned long long r; asm("add.rn.f32x2 %0, %1, %2;" : "=l"(r) : "l"(a), "l"(b)); return r;
}
__device__ __forceinline__ unsigned long long mul2(unsigned long long a, unsigned long long b){
    unsigned long long r; asm("mul.rn.f32x2 %0, %1, %2;" : "=l"(r) : "l"(a), "l"(b)); return r;
}

// mma helpers
__device__ __forceinline__ unsigned smem_u32(const void* p){
    return (unsigned)__cvta_generic_to_shared(p);
}
__device__ __forceinline__ void ldmA(unsigned* r, unsigned addr){
    asm volatile("ldmatrix.sync.aligned.m8n8.x4.shared.b16 {%0,%1,%2,%3}, [%4];"
        : "=r"(r[0]),"=r"(r[1]),"=r"(r[2]),"=r"(r[3]) : "r"(addr));
}
__device__ __forceinline__ void ldmB(unsigned& b0, unsigned& b1, unsigned addr){
    asm volatile("ldmatrix.sync.aligned.m8n8.x2.trans.shared.b16 {%0,%1}, [%2];"
        : "=r"(b0),"=r"(b1) : "r"(addr));
}
__device__ __forceinline__ void mma16816(float* d, const unsigned* a, const unsigned* b){
    asm volatile("mma.sync.aligned.m16n8k16.row.col.f32.f16.f16.f32 "
        "{%0,%1,%2,%3}, {%4,%5,%6,%7}, {%8,%9}, {%0,%1,%2,%3};"
        : "+f"(d[0]),"+f"(d[1]),"+f"(d[2]),"+f"(d[3])
        : "r"(a[0]),"r"(a[1]),"r"(a[2]),"r"(a[3]), "r"(b[0]),"r"(b[1]));
}

// =========================================================================
// FPS: one block/batch, 1024 thr x 4 pts in regs (packed f32x2 pairs).
// Pairwise local argmax tree (ties -> left = first occurrence).
// 32 warp winners -> exactly one redux round.
// =========================================================================
__global__ void __launch_bounds__(1024) fps_kernel(const float* __restrict__ xyz,
                                                   float* __restrict__ out_cxyz)
{
    extern __shared__ float fsm[];
    float* sxx = fsm; float* syy = fsm + NN; float* szz = fsm + 2*NN;
    __shared__ unsigned swd[2][32];
    __shared__ unsigned swi[2][32];

    const int b   = blockIdx.x;
    const int tid = threadIdx.x;
    const float* bx = xyz + (size_t)b * NN * 3;

    for (int idx = tid; idx < NN; idx += 1024) {
        sxx[idx] = bx[idx*3+0]; syy[idx] = bx[idx*3+1]; szz[idx] = bx[idx*3+2];
    }
    __syncthreads();

    unsigned long long pxp[2], pyp[2], pzp[2];
    #pragma unroll
    for (int j = 0; j < 2; j++) {
        int p0 = tid*4 + 2*j;
        pxp[j] = pack2(sxx[p0], sxx[p0+1]);
        pyp[j] = pack2(syy[p0], syy[p0+1]);
        pzp[j] = pack2(szz[p0], szz[p0+1]);
    }
    float dmin[4];
    float c0x = sxx[0], c0y = syy[0], c0z = szz[0];
    {
        unsigned long long ncx = pack2(-c0x, -c0x);
        unsigned long long ncy = pack2(-c0y, -c0y);
        unsigned long long ncz = pack2(-c0z, -c0z);
        #pragma unroll
        for (int j = 0; j < 2; j++) {
            unsigned long long dx = add2(pxp[j], ncx);
            unsigned long long dy = add2(pyp[j], ncy);
            unsigned long long dz = add2(pzp[j], ncz);
            unsigned long long s = add2(add2(mul2(dx,dx), mul2(dy,dy)), mul2(dz,dz));
            unpack2(s, dmin[2*j], dmin[2*j+1]);
        }
    }
    if (tid == 0) {
        out_cxyz[(size_t)b*SS*3+0] = c0x;
        out_cxyz[(size_t)b*SS*3+1] = c0y;
        out_cxyz[(size_t)b*SS*3+2] = c0z;
    }

    const int lane = tid & 31, warp = tid >> 5;
    const unsigned full = 0xFFFFFFFFu;

    float db; int bi_;
    {
        float v2a, v2b; int i2a, i2b;
        { bool l = dmin[0] >= dmin[1]; v2a = l ? dmin[0] : dmin[1]; i2a = l ? 0 : 1; }
        { bool l = dmin[2] >= dmin[3]; v2b = l ? dmin[2] : dmin[3]; i2b = l ? 2 : 3; }
        bool l = v2a >= v2b;
        db = l ? v2a : v2b;
        bi_ = tid*4 + (l ? i2a : i2b);
    }

    for (int t = 1; t < SS; t++) {
        unsigned dmax = __reduce_max_sync(full, __float_as_uint(db));
        unsigned cand = (__float_as_uint(db) == dmax) ? (unsigned)bi_ : 0xFFFFFFFFu;
        unsigned imin = __reduce_min_sync(full, cand);
        if (lane == 0) { swd[t&1][warp] = dmax; swi[t&1][warp] = imin; }
        __syncthreads();

        unsigned wd = swd[t&1][lane];
        unsigned wi = swi[t&1][lane];
        unsigned gmax  = __reduce_max_sync(full, wd);
        unsigned gcand = (wd == gmax) ? wi : 0xFFFFFFFFu;
        int idx = (int)__reduce_min_sync(full, gcand);

        float cx = sxx[idx], cy = syy[idx], cz = szz[idx];
        if (tid == 0) {
            out_cxyz[((size_t)b*SS + t)*3+0] = cx;
            out_cxyz[((size_t)b*SS + t)*3+1] = cy;
            out_cxyz[((size_t)b*SS + t)*3+2] = cz;
        }
        unsigned long long ncx = pack2(-cx, -cx);
        unsigned long long ncy = pack2(-cy, -cy);
        unsigned long long ncz = pack2(-cz, -cz);
        #pragma unroll
        for (int j = 0; j < 2; j++) {
            unsigned long long dx = add2(pxp[j], ncx);
            unsigned long long dy = add2(pyp[j], ncy);
            unsigned long long dz = add2(pzp[j], ncz);
            unsigned long long s = add2(add2(mul2(dx,dx), mul2(dy,dy)), mul2(dz,dz));
            float lo, hi; unpack2(s, lo, hi);
            dmin[2*j]   = fminf(dmin[2*j],   lo);
            dmin[2*j+1] = fminf(dmin[2*j+1], hi);
        }
        float v2a, v2b; int i2a, i2b;
        { bool l = dmin[0] >= dmin[1]; v2a = l ? dmin[0] : dmin[1]; i2a = l ? 0 : 1; }
        { bool l = dmin[2] >= dmin[3]; v2b = l ? dmin[2] : dmin[3]; i2b = l ? 2 : 3; }
        bool l = v2a >= v2b;
        db = l ? v2a : v2b;
        bi_ = tid*4 + (l ? i2a : i2b);
    }
}

// =========================================================================
// kNN: 4 centers per streaming pass, pair-threshold eviction (bit-identical
// selection policy to reference top_k). 48KB static staging.
// =========================================================================
__global__ void __launch_bounds__(256) knn_kernel(const float* __restrict__ xyz,
                                                  const float* __restrict__ cxyz)
{
    __shared__ float sx[NN], sy[NN], sz[NN];
    const int b     = blockIdx.x >> 5;
    const int blkin = blockIdx.x & 31;
    const int tid   = threadIdx.x;
    const float* bx = xyz + (size_t)b * NN * 3;

    for (int j = tid; j < NN; j += 256) {
        sx[j] = bx[j*3+0]; sy[j] = bx[j*3+1]; sz[j] = bx[j*3+2];
    }
    __syncthreads();

    const int warp = tid >> 5, lane = tid & 31;
    const unsigned full = 0xFFFFFFFFu;
    const int sbase = (blkin * 8 + warp) * 4;

    float ax[4], ay[4], az[4], ra[4];
    #pragma unroll
    for (int m = 0; m < 4; m++) {
        ax[m] = cxyz[((size_t)b*SS + sbase + m)*3+0];
        ay[m] = cxyz[((size_t)b*SS + sbase + m)*3+1];
        az[m] = cxyz[((size_t)b*SS + sbase + m)*3+2];
        ra[m] = __fadd_rn(__fadd_rn(__fmul_rn(ax[m],ax[m]), __fmul_rn(ay[m],ay[m])),
                          __fmul_rn(az[m],az[m]));
    }

    unsigned hdu[4]; int hi[4]; unsigned thr_d[4]; int thr_i[4];
    {
        float bxx = sx[lane], byy = sy[lane], bzz = sz[lane];
        float rb  = __fadd_rn(__fadd_rn(__fmul_rn(bxx,bxx), __fmul_rn(byy,byy)), __fmul_rn(bzz,bzz));
        #pragma unroll
        for (int m = 0; m < 4; m++) {
            float dot = __fadd_rn(__fadd_rn(__fmul_rn(ax[m],bxx), __fmul_rn(ay[m],byy)), __fmul_rn(az[m],bzz));
            float d = fmaxf(__fsub_rn(__fadd_rn(ra[m], rb), __fmul_rn(2.0f, dot)), 0.0f);
            hdu[m] = __float_as_uint(d);
            hi[m] = lane;
            thr_d[m] = __reduce_max_sync(full, hdu[m]);
            thr_i[m] = __reduce_max_sync(full, (hdu[m] == thr_d[m]) ? hi[m] : -1);
        }
    }

    for (int j0 = 32; j0 < NN; j0 += 32) {
        int j = j0 + lane;
        float bxx = sx[j], byy = sy[j], bzz = sz[j];
        float rb  = __fadd_rn(__fadd_rn(__fmul_rn(bxx,bxx), __fmul_rn(byy,byy)), __fmul_rn(bzz,bzz));
        unsigned du[4];
        #pragma unroll
        for (int m = 0; m < 4; m++) {
            float dot = __fadd_rn(__fadd_rn(__fmul_rn(ax[m],bxx), __fmul_rn(ay[m],byy)), __fmul_rn(az[m],bzz));
            float d = fmaxf(__fsub_rn(__fadd_rn(ra[m], rb), __fmul_rn(2.0f, dot)), 0.0f);
            du[m] = __float_as_uint(d);
        }
        #pragma unroll
        for (int m = 0; m < 4; m++) {
            unsigned cm = __ballot_sync(full, du[m] < thr_d[m]);
            while (cm) {
                int src = __ffs(cm) - 1;
                cm &= cm - 1;
                unsigned cd = __shfl_sync(full, du[m], src);
                int ci = j0 + src;
                if (cd < thr_d[m]) {
                    if (hdu[m] == thr_d[m] && hi[m] == thr_i[m]) { hdu[m] = cd; hi[m] = ci; }
                    thr_d[m] = __reduce_max_sync(full, hdu[m]);
                    thr_i[m] = __reduce_max_sync(full, (hdu[m] == thr_d[m]) ? hi[m] : -1);
                }
            }
        }
    }
    #pragma unroll
    for (int m = 0; m < 4; m++)
        g_gidx[((size_t)b*SS + sbase + m)*KK + lane] = hi[m];
}

// =========================================================================
// G stats + fused BN1 solve (last block via counter; deterministic).
// =========================================================================
__global__ void __launch_bounds__(256) gstats_kernel(const float* __restrict__ xyz,
                                                     const float* __restrict__ feat,
                                                     const float* __restrict__ cxyz,
                                                     const float* __restrict__ W1,
                                                     const float* __restrict__ g1v,
                                                     const float* __restrict__ b1v)
{
    const int tid = threadIdx.x;
    const int t0  = blockIdx.x * 1024 + tid;
    float s[9]; float m2[45];
    #pragma unroll
    for (int i = 0; i < 9; i++) s[i] = 0.f;
    #pragma unroll
    for (int i = 0; i < 45; i++) m2[i] = 0.f;

    #pragma unroll
    for (int m = 0; m < 4; m++) {
        int r = t0 + m*256;
        int bb = r >> 15, ssi = (r >> 5) & (SS-1);
        int gi = __ldg(&g_gidx[r]);
        const float* c = cxyz + ((size_t)bb*SS + ssi)*3;
        const float* p = xyz  + ((size_t)bb*NN + gi)*3;
        const float* f = feat + ((size_t)bb*NN + gi)*DD;
        float g[9];
        g[0] = __ldg(&p[0]) - __ldg(&c[0]);
        g[1] = __ldg(&p[1]) - __ldg(&c[1]);
        g[2] = __ldg(&p[2]) - __ldg(&c[2]);
        #pragma unroll
        for (int i = 0; i < DD; i++) g[3+i] = __ldg(&f[i]);
        #pragma unroll
        for (int i = 0; i < 9; i++) s[i] += g[i];
        int k = 0;
        #pragma unroll
        for (int i = 0; i < 9; i++)
            #pragma unroll
            for (int j = i; j < 9; j++) { m2[k] = fmaf(g[i], g[j], m2[k]); k++; }
    }
    const unsigned full = 0xFFFFFFFFu;
    #pragma unroll
    for (int q = 0; q < 9; q++)
        for (int o = 16; o > 0; o >>= 1) s[q] += __shfl_xor_sync(full, s[q], o);
    #pragma unroll
    for (int q = 0; q < 45; q++)
        for (int o = 16; o > 0; o >>= 1) m2[q] += __shfl_xor_sync(full, m2[q], o);

    __shared__ float sred[8][56];
    const int lane = tid & 31, warp = tid >> 5;
    if (lane == 0) {
        #pragma unroll
        for (int q = 0; q < 9; q++)  sred[warp][q]   = s[q];
        #pragma unroll
        for (int q = 0; q < 45; q++) sred[warp][9+q] = m2[q];
    }
    __syncthreads();
    if (tid < 54) {
        float a = 0.f;
        #pragma unroll
        for (int w = 0; w < 8; w++) a += sred[w][tid];
        g_gstat[blockIdx.x*64 + tid] = a;
    }

    __shared__ unsigned is_last;
    __threadfence();
    if (tid == 0) is_last = (atomicAdd(&g_ctr1, 1u) == GSB - 1);
    __syncthreads();
    if (!is_last) return;

    __shared__ float part[4][64];
    __shared__ double st[54];
    {
        const int c = tid & 63, r4 = tid >> 6;
        float a0 = 0.f, a1 = 0.f;
        for (int p = r4; p < GSB; p += 8) {
            a0 += g_gstat[p*64 + c];
            a1 += g_gstat[(p+4)*64 + c];
        }
        part[r4][c] = a0 + a1;
    }
    __syncthreads();
    if (tid < 54) st[tid] = (double)(part[0][tid] + part[1][tid] + part[2][tid] + part[3][tid]);
    __syncthreads();
    if (tid < 64) {
        const int t = tid;
        const double Ri = 1.0 / 524288.0;
        double w[9];
        #pragma unroll
        for (int i = 0; i < 9; i++) w[i] = (double)__ldg(&W1[i*64 + t]);
        double m1 = 0.0;
        #pragma unroll
        for (int i = 0; i < 9; i++) m1 += st[i]*Ri*w[i];
        double e2 = 0.0; int k = 0;
        #pragma unroll
        for (int i = 0; i < 9; i++)
            #pragma unroll
            for (int j = i; j < 9; j++) {
                double term = st[9+k]*Ri*w[i]*w[j];
                e2 += (i == j) ? term : 2.0*term;
                k++;
            }
        double var = e2 - m1*m1;
        double sc = (double)__ldg(&g1v[t]) / sqrt(var + 1e-5);
        g_s1[t]  = (float)sc;
        g_b1o[t] = (float)((double)__ldg(&b1v[t]) - m1*sc);
    }
    if (tid == 0) g_ctr1 = 0u;
}

// =========================================================================
// Fused layer1+2 via mma.sync fp16 (stats inline, coalesced x2 stores).
// =========================================================================
__global__ void __launch_bounds__(256) layer12_mma(const float* __restrict__ xyz,
                                                   const float* __restrict__ feat,
                                                   const float* __restrict__ cxyz,
                                                   const float* __restrict__ W1,
                                                   const float* __restrict__ W2)
{
    __shared__ __half w2h[64*72];
    __shared__ __half h1s[128*72];
    __shared__ float sg[128*10];
    __shared__ float rs[8][64], rq[8][64];

    const int tid = threadIdx.x;
    const int rowbase = blockIdx.x * 128;
    const int warp = tid >> 5, lane = tid & 31;
    const unsigned full = 0xFFFFFFFFu;

    for (int i = tid; i < 4096; i += 256) {
        int k = i >> 6, n = i & 63;
        w2h[k*72 + n] = __float2half(__ldg(&W2[i]));
    }

    if (tid < 128) {
        int r = rowbase + tid;
        int bb = r >> 15, ssi = (r >> 5) & (SS-1);
        int gi = __ldg(&g_gidx[r]);
        const float* c = cxyz + ((size_t)bb*SS + ssi)*3;
        const float* p = xyz  + ((size_t)bb*NN + gi)*3;
        const float* f = feat + ((size_t)bb*NN + gi)*DD;
        float* gg = sg + tid*10;
        gg[0] = __ldg(&p[0]) - __ldg(&c[0]);
        gg[1] = __ldg(&p[1]) - __ldg(&c[1]);
        gg[2] = __ldg(&p[2]) - __ldg(&c[2]);
        #pragma unroll
        for (int i = 0; i < DD; i++) gg[3+i] = __ldg(&f[i]);
    }
    __syncthreads();

    {
        const int c2 = tid & 31, r0 = tid >> 5;
        float wa[9], wb[9];
        #pragma unroll
        for (int i = 0; i < 9; i++) {
            wa[i] = __ldg(&W1[i*64 + 2*c2]);
            wb[i] = __ldg(&W1[i*64 + 2*c2 + 1]);
        }
        const float sa = g_s1[2*c2], sb = g_s1[2*c2+1];
        const float ba = g_b1o[2*c2], bbv = g_b1o[2*c2+1];
        #pragma unroll 4
        for (int m = 0; m < 16; m++) {
            int row = r0 + 8*m;
            const float* gg = sg + row*10;
            float xa = gg[0]*wa[0], xb = gg[0]*wb[0];
            #pragma unroll
            for (int i = 1; i < 9; i++) { float gv = gg[i]; xa = fmaf(gv, wa[i], xa); xb = fmaf(gv, wb[i], xb); }
            float ha = fmaxf(fmaf(xa, sa, ba), 0.f);
            float hb = fmaxf(fmaf(xb, sb, bbv), 0.f);
            *(__half2*)&h1s[row*72 + 2*c2] = __floats2half2_rn(ha, hb);
        }
    }
    __syncthreads();

    unsigned af[4][4];
    #pragma unroll
    for (int kt = 0; kt < 4; kt++) {
        unsigned addr = smem_u32(&h1s[(warp*16 + (lane & 15))*72 + kt*16 + (lane >> 4)*8]);
        ldmA(af[kt], addr);
    }
    __syncthreads();

    #pragma unroll
    for (int nt = 0; nt < 8; nt++) {
        unsigned bf[4][2];
        #pragma unroll
        for (int kt = 0; kt < 4; kt++) {
            unsigned addr = smem_u32(&w2h[(kt*16 + (lane & 15))*72 + nt*8]);
            ldmB(bf[kt][0], bf[kt][1], addr);
        }
        float c[4] = {0.f, 0.f, 0.f, 0.f};
        #pragma unroll
        for (int kt = 0; kt < 4; kt++) mma16816(c, af[kt], bf[kt]);

        {
            int r0s = warp*16 + (lane >> 2);
            int h2c = nt*4 + (lane & 3);
            *(__half2*)&h1s[r0s*72 + 2*h2c]     = __floats2half2_rn(c[0], c[1]);
            *(__half2*)&h1s[(r0s+8)*72 + 2*h2c] = __floats2half2_rn(c[2], c[3]);
        }
        float s0 = c[0] + c[2], s1 = c[1] + c[3];
        float q0 = fmaf(c[0], c[0], c[2]*c[2]);
        float q1 = fmaf(c[1], c[1], c[3]*c[3]);
        #pragma unroll
        for (int o = 4; o < 32; o <<= 1) {
            s0 += __shfl_xor_sync(full, s0, o);
            s1 += __shfl_xor_sync(full, s1, o);
            q0 += __shfl_xor_sync(full, q0, o);
            q1 += __shfl_xor_sync(full, q1, o);
        }
        if (lane < 4) {
            int col = nt*8 + 2*lane;
            rs[warp][col]     = s0; rs[warp][col + 1] = s1;
            rq[warp][col]     = q0; rq[warp][col + 1] = q1;
        }
    }
    __syncthreads();

    {
        char* dst = (char*)(g_x2h + (size_t)rowbase*32);
        const char* srcs = (const char*)h1s;
        #pragma unroll
        for (int j = 0; j < 4; j++) {
            int o = tid*16 + j*4096;
            int row = o >> 7, colb = o & 127;
            uint4 v = *(const uint4*)(srcs + row*144 + colb);
            *(uint4*)(dst + o) = v;
        }
    }
    if (tid < 64) {
        float a = 0.f, qq = 0.f;
        #pragma unroll
        for (int w = 0; w < 8; w++) { a += rs[w][tid]; qq += rq[w][tid]; }
        g_part2[blockIdx.x*128 + tid]      = a;
        g_part2[blockIdx.x*128 + 64 + tid] = qq;
    }
}

// -------- BN2: merged two-stage reduction (last-block finalize) --------
__global__ void __launch_bounds__(256) bn2_kernel(const float* __restrict__ g,
                                                  const float* __restrict__ bv)
{
    const int tid = threadIdx.x;
    {
        const int h = tid >> 7, c = tid & 127;
        float a = 0.f;
        #pragma unroll 8
        for (int j = 0; j < 64; j++) {
            int p = blockIdx.x*128 + h + 2*j;
            a += g_part2[p*128 + c];
        }
        __shared__ float sm[256];
        sm[tid] = a;
        __syncthreads();
        if (tid < 128) g_p2b[blockIdx.x*128 + tid] = sm[tid] + sm[tid + 128];
    }
    __shared__ unsigned is_last;
    __threadfence();
    if (tid == 0) is_last = (atomicAdd(&g_ctr2, 1u) == 31);
    __syncthreads();
    if (!is_last) return;

    if (tid < 64) {
        float s = 0.f, q = 0.f;
        #pragma unroll 8
        for (int b = 0; b < 32; b++) {
            s += g_p2b[b*128 + tid];
            q += g_p2b[b*128 + 64 + tid];
        }
        float m = s * (1.0f/524288.0f);
        float v = q * (1.0f/524288.0f) - m*m;
        float sc = __ldg(&g[tid]) * rsqrtf(v + 1e-5f);
        g_s2[tid] = sc; g_b2o[tid] = __ldg(&bv[tid]) - m*sc;
    }
    if (tid == 0) g_ctr2 = 0u;
}

// =========================================================================
// Layer 3 via mma.sync fp16 tensor cores.
// =========================================================================
__global__ void __launch_bounds__(256) layer3_mma(const float* __restrict__ W3)
{
    __shared__ __half w3h[64*136];
    __shared__ __half h2s[2][32*72];
    __shared__ float s2s[64], b2s[64];

    const int tid = threadIdx.x;
    const int warp = tid >> 5, lane = tid & 31;
    const int sub = warp >> 2;
    const int wq  = warp & 3;
    const int n0  = wq * 32;
    const unsigned full = 0xFFFFFFFFu;

    for (int i = tid; i < 8192; i += 256) {
        int k = i >> 7, n = i & 127;
        w3h[k*136 + n] = __float2half(__ldg(&W3[i]));
    }
    if (tid < 64) { s2s[tid] = g_s2[tid]; b2s[tid] = g_b2o[tid]; }
    __syncthreads();

    unsigned bfrag[4][4][2];
    #pragma unroll
    for (int nt = 0; nt < 4; nt++)
        #pragma unroll
        for (int kt = 0; kt < 4; kt++) {
            unsigned addr = smem_u32(&w3h[(kt*16 + (lane & 15))*136 + n0 + nt*8]);
            ldmB(bfrag[nt][kt][0], bfrag[nt][kt][1], addr);
        }

    const int tid128 = tid & 127;
    const int kkrow  = tid128 >> 2;
    const int cg     = (tid128 & 3) * 8;

    for (int cc = 0; cc < 8; cc++) {
        const int bs = blockIdx.x*16 + cc*2 + sub;
        __syncthreads();

        {
            const __half2* src = &g_x2h[((size_t)bs*KK + kkrow)*32 + cg];
            uint4 v0 = *(const uint4*)(src);
            uint4 v1 = *(const uint4*)(src + 4);
            unsigned vv[8] = {v0.x, v0.y, v0.z, v0.w, v1.x, v1.y, v1.z, v1.w};
            #pragma unroll
            for (int j = 0; j < 8; j++) {
                __half2 hv = *(__half2*)&vv[j];
                float2 f = __half22float2(hv);
                int ch = 2*(cg + j);
                float ha = fmaxf(fmaf(f.x, s2s[ch],   b2s[ch]),   0.f);
                float hb = fmaxf(fmaf(f.y, s2s[ch+1], b2s[ch+1]), 0.f);
                *(__half2*)&h2s[sub][kkrow*72 + ch] = __floats2half2_rn(ha, hb);
            }
        }
        __syncthreads();

        unsigned af[2][4][4];
        #pragma unroll
        for (int mt = 0; mt < 2; mt++)
            #pragma unroll
            for (int kt = 0; kt < 4; kt++) {
                unsigned addr = smem_u32(&h2s[sub][(mt*16 + (lane & 15))*72
                                                   + kt*16 + (lane >> 4)*8]);
                ldmA(af[mt][kt], addr);
            }

        const size_t bs128 = (size_t)bs*128;
        const size_t bs256 = (size_t)bs*256;

        #pragma unroll
        for (int nt = 0; nt < 4; nt++) {
            float ac[2][4];
            #pragma unroll
            for (int mt = 0; mt < 2; mt++) {
                ac[mt][0] = 0.f; ac[mt][1] = 0.f; ac[mt][2] = 0.f; ac[mt][3] = 0.f;
                #pragma unroll
                for (int kt = 0; kt < 4; kt++)
                    mma16816(ac[mt], af[mt][kt], bfrag[nt][kt]);
            }
            float mx0 = fmaxf(fmaxf(ac[0][0], ac[0][2]), fmaxf(ac[1][0], ac[1][2]));
            float mx1 = fmaxf(fmaxf(ac[0][1], ac[0][3]), fmaxf(ac[1][1], ac[1][3]));
            float mn0 = fminf(fminf(ac[0][0], ac[0][2]), fminf(ac[1][0], ac[1][2]));
            float mn1 = fminf(fminf(ac[0][1], ac[0][3]), fminf(ac[1][1], ac[1][3]));
            float sm0 = (ac[0][0] + ac[0][2]) + (ac[1][0] + ac[1][2]);
            float sm1 = (ac[0][1] + ac[0][3]) + (ac[1][1] + ac[1][3]);
            float sq0 = fmaf(ac[0][0],ac[0][0], fmaf(ac[0][2],ac[0][2],
                        fmaf(ac[1][0],ac[1][0], ac[1][2]*ac[1][2])));
            float sq1 = fmaf(ac[0][1],ac[0][1], fmaf(ac[0][3],ac[0][3],
                        fmaf(ac[1][1],ac[1][1], ac[1][3]*ac[1][3])));
            #pragma unroll
            for (int o = 4; o < 32; o <<= 1) {
                mx0 = fmaxf(mx0, __shfl_xor_sync(full, mx0, o));
                mx1 = fmaxf(mx1, __shfl_xor_sync(full, mx1, o));
                mn0 = fminf(mn0, __shfl_xor_sync(full, mn0, o));
                mn1 = fminf(mn1, __shfl_xor_sync(full, mn1, o));
                sm0 += __shfl_xor_sync(full, sm0, o);
                sm1 += __shfl_xor_sync(full, sm1, o);
                sq0 += __shfl_xor_sync(full, sq0, o);
                sq1 += __shfl_xor_sync(full, sq1, o);
            }
            if (lane < 4) {
                int col = n0 + nt*8 + 2*lane;
                g_max3[bs128 + col]     = mx0;
                g_max3[bs128 + col + 1] = mx1;
                g_min3[bs128 + col]     = mn0;
                g_min3[bs128 + col + 1] = mn1;
                g_part3[bs256 + col]           = sm0;
                g_part3[bs256 + col + 1]       = sm1;
                g_part3[bs256 + 128 + col]     = sq0;
                g_part3[bs256 + 128 + col + 1] = sq1;
            }
        }
    }
}

// -------- BN3: merged two-stage reduction (last-block finalize) --------
__global__ void __launch_bounds__(256) bn3_kernel(const float* __restrict__ g,
                                                  const float* __restrict__ bv)
{
    const int tid = threadIdx.x;
    {
        float a = 0.f;
        #pragma unroll 8
        for (int p = 0; p < 128; p++)
            a += g_part3[((size_t)blockIdx.x*128 + p)*256 + tid];
        g_p3b[blockIdx.x*256 + tid] = a;
    }
    __shared__ unsigned is_last;
    __threadfence();
    if (tid == 0) is_last = (atomicAdd(&g_ctr3, 1u) == 127);
    __syncthreads();
    if (!is_last) return;

    {
        const int h = tid >> 7, c = tid & 127;
        float s = 0.f, q = 0.f;
        #pragma unroll 8
        for (int j = 0; j < 64; j++) {
            int b = h + 2*j;
            s += g_p3b[b*256 + c];
            q += g_p3b[b*256 + 128 + c];
        }
        __shared__ float ssm[256], qsm[256];
        ssm[tid] = s; qsm[tid] = q;
        __syncthreads();
        if (tid < 128) {
            float ts = ssm[tid] + ssm[tid + 128];
            float tq = qsm[tid] + qsm[tid + 128];
            float m = ts * (1.0f/524288.0f);
            float v = tq * (1.0f/524288.0f) - m*m;
            float sc = __ldg(&g[tid]) * rsqrtf(v + 1e-5f);
            g_s3[tid] = sc; g_b3o[tid] = __ldg(&bv[tid]) - m*sc;
        }
    }
    if (tid == 0) g_ctr3 = 0u;
}

// max_k relu(s*x+b) = relu(s*(s>=0? max:min) + b)
__global__ void final_kernel(float* __restrict__ out_feat)
{
    int idx = blockIdx.x * 256 + threadIdx.x;
    int c = idx & 127;
    float sc = g_s3[c], bi = g_b3o[c];
    float v = (sc >= 0.f) ? g_max3[idx] : g_min3[idx];
    out_feat[idx] = fmaxf(fmaf(v, sc, bi), 0.f);
}

// =========================================================================
extern "C" void kernel_launch(void* const* d_in, const int* in_sizes, int n_in,
                              void* d_out, int out_size)
{
    const float* xyz  = (const float*)d_in[0];
    const float* feat = (const float*)d_in[1];
    const float* W1   = (const float*)d_in[2];
    const float* g1   = (const float*)d_in[3];
    const float* b1   = (const float*)d_in[4];
    const float* W2   = (const float*)d_in[5];
    const float* g2   = (const float*)d_in[6];
    const float* b2   = (const float*)d_in[7];
    const float* W3   = (const float*)d_in[8];
    const float* g3   = (const float*)d_in[9];
    const float* b3   = (const float*)d_in[10];

    float* out   = (float*)d_out;
    float* cxyz  = out;                      // [16,1024,3]
    float* ofeat = out + (size_t)BB*SS*3;    // [16,1024,128]

    cudaFuncSetAttribute(fps_kernel, cudaFuncAttributeMaxDynamicSharedMemorySize, NN*3*4);

    fps_kernel    <<<BB, 1024, NN*3*4>>>(xyz, cxyz);
    knn_kernel    <<<BB*KNN_BPB, 256>>>(xyz, cxyz);
    gstats_kernel <<<GSB, 256>>>(xyz, feat, cxyz, W1, g1, b1);
    layer12_mma   <<<NB2, 256>>>(xyz, feat, cxyz, W1, W2);
    bn2_kernel    <<<32, 256>>>(g2, b2);
    layer3_mma    <<<NCTR/16, 256>>>(W3);
    bn3_kernel    <<<128, 256>>>(g3, b3);
    final_kernel  <<<(BB*SS*128)/256, 256>>>(ofeat);
}

// round 15
// speedup vs baseline: 1.2703x; 1.2065x over previous
#include <cuda_runtime.h>
#include <cuda_fp16.h>

// Problem constants
#define BB 16
#define NN 4096
#define DD 6
#define SS 1024          // NUM_CENTERS
#define KK 32
#define ROWS (BB*SS*KK)  // 524288
#define NB2  4096        // layer12 blocks (128 rows each)
#define NCTR (BB*SS)     // 16384 centers
#define GSB 512          // gstats blocks
#define KNNB 128         // knn blocks in merged kernel (8 per batch)
#define MERGED_SMEM 122880  // 120KB -> 1 block/SM, 144 blocks = single wave

// ---------------- device scratch ----------------
__device__ int   g_gidx[ROWS];                       // 2 MB
__device__ __half2 g_x2h[(size_t)ROWS*32];           // 64 MB (fp16 x2)
__device__ float g_gstat[GSB*64];
__device__ float g_part2[NB2*128];
__device__ float g_p2b[32*128];
__device__ float g_part3[(size_t)NCTR*256];
__device__ float g_p3b[128*256];
__device__ float g_max3[(size_t)NCTR*128];
__device__ float g_min3[(size_t)NCTR*128];
__device__ float g_s1[64], g_b1o[64], g_s2[64], g_b2o[64], g_s3[128], g_b3o[128];
__device__ unsigned g_ctr1, g_ctr2, g_ctr3;
__device__ volatile unsigned g_prog[BB];             // fps progress per batch

// packed f32x2 helpers
__device__ __forceinline__ unsigned long long pack2(float lo, float hi){
    unsigned long long r;
    asm("mov.b64 %0, {%1, %2};" : "=l"(r) : "f"(lo), "f"(hi));
    return r;
}
__device__ __forceinline__ void unpack2(unsigned long long v, float& lo, float& hi){
    asm("mov.b64 {%0, %1}, %2;" : "=f"(lo), "=f"(hi) : "l"(v));
}
__device__ __forceinline__ unsigned long long add2(unsigned long long a, unsigned long long b){
    unsigned long long r; asm("add.rn.f32x2 %0, %1, %2;" : "=l"(r) : "l"(a), "l"(b)); return r;
}
__device__ __forceinline__ unsigned long long mul2(unsigned long long a, unsigned long long b){
    unsigned long long r; asm("mul.rn.f32x2 %0, %1, %2;" : "=l"(r) : "l"(a), "l"(b)); return r;
}

// mma helpers
__device__ __forceinline__ unsigned smem_u32(const void* p){
    return (unsigned)__cvta_generic_to_shared(p);
}
__device__ __forceinline__ void ldmA(unsigned* r, unsigned addr){
    asm volatile("ldmatrix.sync.aligned.m8n8.x4.shared.b16 {%0,%1,%2,%3}, [%4];"
        : "=r"(r[0]),"=r"(r[1]),"=r"(r[2]),"=r"(r[3]) : "r"(addr));
}
__device__ __forceinline__ void ldmB(unsigned& b0, unsigned& b1, unsigned addr){
    asm volatile("ldmatrix.sync.aligned.m8n8.x2.trans.shared.b16 {%0,%1}, [%2];"
        : "=r"(b0),"=r"(b1) : "r"(addr));
}
__device__ __forceinline__ void mma16816(float* d, const unsigned* a, const unsigned* b){
    asm volatile("mma.sync.aligned.m16n8k16.row.col.f32.f16.f16.f32 "
        "{%0,%1,%2,%3}, {%4,%5,%6,%7}, {%8,%9}, {%0,%1,%2,%3};"
        : "+f"(d[0]),"+f"(d[1]),"+f"(d[2]),"+f"(d[3])
        : "r"(a[0]),"r"(a[1]),"r"(a[2]),"r"(a[3]), "r"(b[0]),"r"(b[1]));
}

// =========================================================================
// Merged FPS + kNN, single wave (144 blocks, 1/SM).
// Blocks 0..15: FPS (1024 thr x 4 pts, pairwise argmax tree, publish /16).
// Blocks 16..143: kNN (32 warps x 4 centers, interleaved groups, wait on
// g_prog). Candidate order per center identical -> bit-identical selection.
// =========================================================================
__global__ void __launch_bounds__(1024) fps_knn_kernel(const float* __restrict__ xyz,
                                                       float* __restrict__ out_cxyz)
{
    extern __shared__ float fsm[];
    float* sxx = fsm; float* syy = fsm + NN; float* szz = fsm + 2*NN;

    const int tid = threadIdx.x;
    const int lane = tid & 31, warp = tid >> 5;
    const unsigned full = 0xFFFFFFFFu;

    if (blockIdx.x < BB) {
        // ---------------- FPS role ----------------
        __shared__ unsigned swd[2][32];
        __shared__ unsigned swi[2][32];
        const int b = blockIdx.x;
        const float* bx = xyz + (size_t)b * NN * 3;

        for (int idx = tid; idx < NN; idx += 1024) {
            sxx[idx] = bx[idx*3+0]; syy[idx] = bx[idx*3+1]; szz[idx] = bx[idx*3+2];
        }
        __syncthreads();

        unsigned long long pxp[2], pyp[2], pzp[2];
        #pragma unroll
        for (int j = 0; j < 2; j++) {
            int p0 = tid*4 + 2*j;
            pxp[j] = pack2(sxx[p0], sxx[p0+1]);
            pyp[j] = pack2(syy[p0], syy[p0+1]);
            pzp[j] = pack2(szz[p0], szz[p0+1]);
        }
        float dmin[4];
        float c0x = sxx[0], c0y = syy[0], c0z = szz[0];
        {
            unsigned long long ncx = pack2(-c0x, -c0x);
            unsigned long long ncy = pack2(-c0y, -c0y);
            unsigned long long ncz = pack2(-c0z, -c0z);
            #pragma unroll
            for (int j = 0; j < 2; j++) {
                unsigned long long dx = add2(pxp[j], ncx);
                unsigned long long dy = add2(pyp[j], ncy);
                unsigned long long dz = add2(pzp[j], ncz);
                unsigned long long s = add2(add2(mul2(dx,dx), mul2(dy,dy)), mul2(dz,dz));
                unpack2(s, dmin[2*j], dmin[2*j+1]);
            }
        }
        if (tid == 0) {
            out_cxyz[(size_t)b*SS*3+0] = c0x;
            out_cxyz[(size_t)b*SS*3+1] = c0y;
            out_cxyz[(size_t)b*SS*3+2] = c0z;
        }

        float db; int bi_;
        {
            float v2a, v2b; int i2a, i2b;
            { bool l = dmin[0] >= dmin[1]; v2a = l ? dmin[0] : dmin[1]; i2a = l ? 0 : 1; }
            { bool l = dmin[2] >= dmin[3]; v2b = l ? dmin[2] : dmin[3]; i2b = l ? 2 : 3; }
            bool l = v2a >= v2b;
            db = l ? v2a : v2b;
            bi_ = tid*4 + (l ? i2a : i2b);
        }

        for (int t = 1; t < SS; t++) {
            unsigned dmax = __reduce_max_sync(full, __float_as_uint(db));
            unsigned cand = (__float_as_uint(db) == dmax) ? (unsigned)bi_ : 0xFFFFFFFFu;
            unsigned imin = __reduce_min_sync(full, cand);
            if (lane == 0) { swd[t&1][warp] = dmax; swi[t&1][warp] = imin; }
            __syncthreads();

            unsigned wd = swd[t&1][lane];
            unsigned wi = swi[t&1][lane];
            unsigned gmax  = __reduce_max_sync(full, wd);
            unsigned gcand = (wd == gmax) ? wi : 0xFFFFFFFFu;
            int idx = (int)__reduce_min_sync(full, gcand);

            float cx = sxx[idx], cy = syy[idx], cz = szz[idx];
            if (tid == 0) {
                out_cxyz[((size_t)b*SS + t)*3+0] = cx;
                out_cxyz[((size_t)b*SS + t)*3+1] = cy;
                out_cxyz[((size_t)b*SS + t)*3+2] = cz;
                if (((t + 1) & 15) == 0) {       // publish every 16 centers
                    __threadfence();
                    g_prog[b] = (unsigned)(t + 1);
                }
            }
            unsigned long long ncx = pack2(-cx, -cx);
            unsigned long long ncy = pack2(-cy, -cy);
            unsigned long long ncz = pack2(-cz, -cz);
            #pragma unroll
            for (int j = 0; j < 2; j++) {
                unsigned long long dx = add2(pxp[j], ncx);
                unsigned long long dy = add2(pyp[j], ncy);
                unsigned long long dz = add2(pzp[j], ncz);
                unsigned long long s = add2(add2(mul2(dx,dx), mul2(dy,dy)), mul2(dz,dz));
                float lo, hi; unpack2(s, lo, hi);
                dmin[2*j]   = fminf(dmin[2*j],   lo);
                dmin[2*j+1] = fminf(dmin[2*j+1], hi);
            }
            float v2a, v2b; int i2a, i2b;
            { bool l = dmin[0] >= dmin[1]; v2a = l ? dmin[0] : dmin[1]; i2a = l ? 0 : 1; }
            { bool l = dmin[2] >= dmin[3]; v2b = l ? dmin[2] : dmin[3]; i2b = l ? 2 : 3; }
            bool l = v2a >= v2b;
            db = l ? v2a : v2b;
            bi_ = tid*4 + (l ? i2a : i2b);
        }
    } else {
        // ---------------- kNN role ----------------
        const int kb    = blockIdx.x - BB;   // 0..127
        const int b     = kb >> 3;           // batch
        const int blkin = kb & 7;
        const float* bx = xyz + (size_t)b * NN * 3;
        const float* cxyz = out_cxyz;

        for (int j = tid; j < NN; j += 1024) {
            sxx[j] = bx[j*3+0]; syy[j] = bx[j*3+1]; szz[j] = bx[j*3+2];
        }
        __syncthreads();

        // interleaved group: every block gets early AND late centers
        const int sbase = (warp*8 + blkin) * 4;

        if (lane == 0) {
            while (g_prog[b] < (unsigned)(sbase + 4)) __nanosleep(400);
        }
        __syncwarp();
        __threadfence();   // acquire: order center reads after prog observation

        float ax[4], ay[4], az[4], ra[4];
        #pragma unroll
        for (int m = 0; m < 4; m++) {
            ax[m] = __ldcg(&cxyz[((size_t)b*SS + sbase + m)*3+0]);
            ay[m] = __ldcg(&cxyz[((size_t)b*SS + sbase + m)*3+1]);
            az[m] = __ldcg(&cxyz[((size_t)b*SS + sbase + m)*3+2]);
            ra[m] = __fadd_rn(__fadd_rn(__fmul_rn(ax[m],ax[m]), __fmul_rn(ay[m],ay[m])),
                              __fmul_rn(az[m],az[m]));
        }

        unsigned hdu[4]; int hi[4]; unsigned thr_d[4]; int thr_i[4];
        {
            float bxx = sxx[lane], byy = syy[lane], bzz = szz[lane];
            float rb  = __fadd_rn(__fadd_rn(__fmul_rn(bxx,bxx), __fmul_rn(byy,byy)), __fmul_rn(bzz,bzz));
            #pragma unroll
            for (int m = 0; m < 4; m++) {
                float dot = __fadd_rn(__fadd_rn(__fmul_rn(ax[m],bxx), __fmul_rn(ay[m],byy)), __fmul_rn(az[m],bzz));
                float d = fmaxf(__fsub_rn(__fadd_rn(ra[m], rb), __fmul_rn(2.0f, dot)), 0.0f);
                hdu[m] = __float_as_uint(d);
                hi[m] = lane;
                thr_d[m] = __reduce_max_sync(full, hdu[m]);
                thr_i[m] = __reduce_max_sync(full, (hdu[m] == thr_d[m]) ? hi[m] : -1);
            }
        }

        for (int j0 = 32; j0 < NN; j0 += 32) {
            int j = j0 + lane;
            float bxx = sxx[j], byy = syy[j], bzz = szz[j];
            float rb  = __fadd_rn(__fadd_rn(__fmul_rn(bxx,bxx), __fmul_rn(byy,byy)), __fmul_rn(bzz,bzz));
            unsigned du[4];
            #pragma unroll
            for (int m = 0; m < 4; m++) {
                float dot = __fadd_rn(__fadd_rn(__fmul_rn(ax[m],bxx), __fmul_rn(ay[m],byy)), __fmul_rn(az[m],bzz));
                float d = fmaxf(__fsub_rn(__fadd_rn(ra[m], rb), __fmul_rn(2.0f, dot)), 0.0f);
                du[m] = __float_as_uint(d);
            }
            #pragma unroll
            for (int m = 0; m < 4; m++) {
                unsigned cm = __ballot_sync(full, du[m] < thr_d[m]);
                while (cm) {
                    int src = __ffs(cm) - 1;
                    cm &= cm - 1;
                    unsigned cd = __shfl_sync(full, du[m], src);
                    int ci = j0 + src;
                    if (cd < thr_d[m]) {
                        if (hdu[m] == thr_d[m] && hi[m] == thr_i[m]) { hdu[m] = cd; hi[m] = ci; }
                        thr_d[m] = __reduce_max_sync(full, hdu[m]);
                        thr_i[m] = __reduce_max_sync(full, (hdu[m] == thr_d[m]) ? hi[m] : -1);
                    }
                }
            }
        }
        #pragma unroll
        for (int m = 0; m < 4; m++)
            g_gidx[((size_t)b*SS + sbase + m)*KK + lane] = hi[m];
    }
}

// =========================================================================
// G stats + fused BN1 solve (last block via counter; deterministic).
// =========================================================================
__global__ void __launch_bounds__(256) gstats_kernel(const float* __restrict__ xyz,
                                                     const float* __restrict__ feat,
                                                     const float* __restrict__ cxyz,
                                                     const float* __restrict__ W1,
                                                     const float* __restrict__ g1v,
                                                     const float* __restrict__ b1v)
{
    const int tid = threadIdx.x;
    const int t0  = blockIdx.x * 1024 + tid;
    float s[9]; float m2[45];
    #pragma unroll
    for (int i = 0; i < 9; i++) s[i] = 0.f;
    #pragma unroll
    for (int i = 0; i < 45; i++) m2[i] = 0.f;

    #pragma unroll
    for (int m = 0; m < 4; m++) {
        int r = t0 + m*256;
        int bb = r >> 15, ssi = (r >> 5) & (SS-1);
        int gi = __ldg(&g_gidx[r]);
        const float* c = cxyz + ((size_t)bb*SS + ssi)*3;
        const float* p = xyz  + ((size_t)bb*NN + gi)*3;
        const float* f = feat + ((size_t)bb*NN + gi)*DD;
        float g[9];
        g[0] = __ldg(&p[0]) - __ldg(&c[0]);
        g[1] = __ldg(&p[1]) - __ldg(&c[1]);
        g[2] = __ldg(&p[2]) - __ldg(&c[2]);
        #pragma unroll
        for (int i = 0; i < DD; i++) g[3+i] = __ldg(&f[i]);
        #pragma unroll
        for (int i = 0; i < 9; i++) s[i] += g[i];
        int k = 0;
        #pragma unroll
        for (int i = 0; i < 9; i++)
            #pragma unroll
            for (int j = i; j < 9; j++) { m2[k] = fmaf(g[i], g[j], m2[k]); k++; }
    }
    const unsigned full = 0xFFFFFFFFu;
    #pragma unroll
    for (int q = 0; q < 9; q++)
        for (int o = 16; o > 0; o >>= 1) s[q] += __shfl_xor_sync(full, s[q], o);
    #pragma unroll
    for (int q = 0; q < 45; q++)
        for (int o = 16; o > 0; o >>= 1) m2[q] += __shfl_xor_sync(full, m2[q], o);

    __shared__ float sred[8][56];
    const int lane = tid & 31, warp = tid >> 5;
    if (lane == 0) {
        #pragma unroll
        for (int q = 0; q < 9; q++)  sred[warp][q]   = s[q];
        #pragma unroll
        for (int q = 0; q < 45; q++) sred[warp][9+q] = m2[q];
    }
    __syncthreads();
    if (tid < 54) {
        float a = 0.f;
        #pragma unroll
        for (int w = 0; w < 8; w++) a += sred[w][tid];
        g_gstat[blockIdx.x*64 + tid] = a;
    }

    __shared__ unsigned is_last;
    __threadfence();
    if (tid == 0) is_last = (atomicAdd(&g_ctr1, 1u) == GSB - 1);
    __syncthreads();
    if (!is_last) return;

    __shared__ float part[4][64];
    __shared__ double st[54];
    {
        const int c = tid & 63, r4 = tid >> 6;
        float a0 = 0.f, a1 = 0.f;
        for (int p = r4; p < GSB; p += 8) {
            a0 += g_gstat[p*64 + c];
            a1 += g_gstat[(p+4)*64 + c];
        }
        part[r4][c] = a0 + a1;
    }
    __syncthreads();
    if (tid < 54) st[tid] = (double)(part[0][tid] + part[1][tid] + part[2][tid] + part[3][tid]);
    __syncthreads();
    if (tid < 64) {
        const int t = tid;
        const double Ri = 1.0 / 524288.0;
        double w[9];
        #pragma unroll
        for (int i = 0; i < 9; i++) w[i] = (double)__ldg(&W1[i*64 + t]);
        double m1 = 0.0;
        #pragma unroll
        for (int i = 0; i < 9; i++) m1 += st[i]*Ri*w[i];
        double e2 = 0.0; int k = 0;
        #pragma unroll
        for (int i = 0; i < 9; i++)
            #pragma unroll
            for (int j = i; j < 9; j++) {
                double term = st[9+k]*Ri*w[i]*w[j];
                e2 += (i == j) ? term : 2.0*term;
                k++;
            }
        double var = e2 - m1*m1;
        double sc = (double)__ldg(&g1v[t]) / sqrt(var + 1e-5);
        g_s1[t]  = (float)sc;
        g_b1o[t] = (float)((double)__ldg(&b1v[t]) - m1*sc);
    }
    if (tid == 0) g_ctr1 = 0u;
}

// =========================================================================
// Fused layer1+2 via mma.sync fp16 (stats inline, coalesced x2 stores).
// =========================================================================
__global__ void __launch_bounds__(256) layer12_mma(const float* __restrict__ xyz,
                                                   const float* __restrict__ feat,
                                                   const float* __restrict__ cxyz,
                                                   const float* __restrict__ W1,
                                                   const float* __restrict__ W2)
{
    __shared__ __half w2h[64*72];
    __shared__ __half h1s[128*72];
    __shared__ float sg[128*10];
    __shared__ float rs[8][64], rq[8][64];

    const int tid = threadIdx.x;
    const int rowbase = blockIdx.x * 128;
    const int warp = tid >> 5, lane = tid & 31;
    const unsigned full = 0xFFFFFFFFu;

    for (int i = tid; i < 4096; i += 256) {
        int k = i >> 6, n = i & 63;
        w2h[k*72 + n] = __float2half(__ldg(&W2[i]));
    }

    if (tid < 128) {
        int r = rowbase + tid;
        int bb = r >> 15, ssi = (r >> 5) & (SS-1);
        int gi = __ldg(&g_gidx[r]);
        const float* c = cxyz + ((size_t)bb*SS + ssi)*3;
        const float* p = xyz  + ((size_t)bb*NN + gi)*3;
        const float* f = feat + ((size_t)bb*NN + gi)*DD;
        float* gg = sg + tid*10;
        gg[0] = __ldg(&p[0]) - __ldg(&c[0]);
        gg[1] = __ldg(&p[1]) - __ldg(&c[1]);
        gg[2] = __ldg(&p[2]) - __ldg(&c[2]);
        #pragma unroll
        for (int i = 0; i < DD; i++) gg[3+i] = __ldg(&f[i]);
    }
    __syncthreads();

    {
        const int c2 = tid & 31, r0 = tid >> 5;
        float wa[9], wb[9];
        #pragma unroll
        for (int i = 0; i < 9; i++) {
            wa[i] = __ldg(&W1[i*64 + 2*c2]);
            wb[i] = __ldg(&W1[i*64 + 2*c2 + 1]);
        }
        const float sa = g_s1[2*c2], sb = g_s1[2*c2+1];
        const float ba = g_b1o[2*c2], bbv = g_b1o[2*c2+1];
        #pragma unroll 4
        for (int m = 0; m < 16; m++) {
            int row = r0 + 8*m;
            const float* gg = sg + row*10;
            float xa = gg[0]*wa[0], xb = gg[0]*wb[0];
            #pragma unroll
            for (int i = 1; i < 9; i++) { float gv = gg[i]; xa = fmaf(gv, wa[i], xa); xb = fmaf(gv, wb[i], xb); }
            float ha = fmaxf(fmaf(xa, sa, ba), 0.f);
            float hb = fmaxf(fmaf(xb, sb, bbv), 0.f);
            *(__half2*)&h1s[row*72 + 2*c2] = __floats2half2_rn(ha, hb);
        }
    }
    __syncthreads();

    unsigned af[4][4];
    #pragma unroll
    for (int kt = 0; kt < 4; kt++) {
        unsigned addr = smem_u32(&h1s[(warp*16 + (lane & 15))*72 + kt*16 + (lane >> 4)*8]);
        ldmA(af[kt], addr);
    }
    __syncthreads();

    #pragma unroll
    for (int nt = 0; nt < 8; nt++) {
        unsigned bf[4][2];
        #pragma unroll
        for (int kt = 0; kt < 4; kt++) {
            unsigned addr = smem_u32(&w2h[(kt*16 + (lane & 15))*72 + nt*8]);
            ldmB(bf[kt][0], bf[kt][1], addr);
        }
        float c[4] = {0.f, 0.f, 0.f, 0.f};
        #pragma unroll
        for (int kt = 0; kt < 4; kt++) mma16816(c, af[kt], bf[kt]);

        {
            int r0s = warp*16 + (lane >> 2);
            int h2c = nt*4 + (lane & 3);
            *(__half2*)&h1s[r0s*72 + 2*h2c]     = __floats2half2_rn(c[0], c[1]);
            *(__half2*)&h1s[(r0s+8)*72 + 2*h2c] = __floats2half2_rn(c[2], c[3]);
        }
        float s0 = c[0] + c[2], s1 = c[1] + c[3];
        float q0 = fmaf(c[0], c[0], c[2]*c[2]);
        float q1 = fmaf(c[1], c[1], c[3]*c[3]);
        #pragma unroll
        for (int o = 4; o < 32; o <<= 1) {
            s0 += __shfl_xor_sync(full, s0, o);
            s1 += __shfl_xor_sync(full, s1, o);
            q0 += __shfl_xor_sync(full, q0, o);
            q1 += __shfl_xor_sync(full, q1, o);
        }
        if (lane < 4) {
            int col = nt*8 + 2*lane;
            rs[warp][col]     = s0; rs[warp][col + 1] = s1;
            rq[warp][col]     = q0; rq[warp][col + 1] = q1;
        }
    }
    __syncthreads();

    {
        char* dst = (char*)(g_x2h + (size_t)rowbase*32);
        const char* srcs = (const char*)h1s;
        #pragma unroll
        for (int j = 0; j < 4; j++) {
            int o = tid*16 + j*4096;
            int row = o >> 7, colb = o & 127;
            uint4 v = *(const uint4*)(srcs + row*144 + colb);
            *(uint4*)(dst + o) = v;
        }
    }
    if (tid < 64) {
        float a = 0.f, qq = 0.f;
        #pragma unroll
        for (int w = 0; w < 8; w++) { a += rs[w][tid]; qq += rq[w][tid]; }
        g_part2[blockIdx.x*128 + tid]      = a;
        g_part2[blockIdx.x*128 + 64 + tid] = qq;
    }
}

// -------- BN2: merged two-stage reduction (last-block finalize) --------
__global__ void __launch_bounds__(256) bn2_kernel(const float* __restrict__ g,
                                                  const float* __restrict__ bv)
{
    const int tid = threadIdx.x;
    {
        const int h = tid >> 7, c = tid & 127;
        float a = 0.f;
        #pragma unroll 8
        for (int j = 0; j < 64; j++) {
            int p = blockIdx.x*128 + h + 2*j;
            a += g_part2[p*128 + c];
        }
        __shared__ float sm[256];
        sm[tid] = a;
        __syncthreads();
        if (tid < 128) g_p2b[blockIdx.x*128 + tid] = sm[tid] + sm[tid + 128];
    }
    __shared__ unsigned is_last;
    __threadfence();
    if (tid == 0) is_last = (atomicAdd(&g_ctr2, 1u) == 31);
    __syncthreads();
    if (!is_last) return;

    if (tid < 64) {
        float s = 0.f, q = 0.f;
        #pragma unroll 8
        for (int b = 0; b < 32; b++) {
            s += g_p2b[b*128 + tid];
            q += g_p2b[b*128 + 64 + tid];
        }
        float m = s * (1.0f/524288.0f);
        float v = q * (1.0f/524288.0f) - m*m;
        float sc = __ldg(&g[tid]) * rsqrtf(v + 1e-5f);
        g_s2[tid] = sc; g_b2o[tid] = __ldg(&bv[tid]) - m*sc;
    }
    if (tid == 0) g_ctr2 = 0u;
}

// =========================================================================
// Layer 3 via mma.sync fp16 tensor cores.
// =========================================================================
__global__ void __launch_bounds__(256) layer3_mma(const float* __restrict__ W3)
{
    __shared__ __half w3h[64*136];
    __shared__ __half h2s[2][32*72];
    __shared__ float s2s[64], b2s[64];

    const int tid = threadIdx.x;
    const int warp = tid >> 5, lane = tid & 31;
    const int sub = warp >> 2;
    const int wq  = warp & 3;
    const int n0  = wq * 32;
    const unsigned full = 0xFFFFFFFFu;

    for (int i = tid; i < 8192; i += 256) {
        int k = i >> 7, n = i & 127;
        w3h[k*136 + n] = __float2half(__ldg(&W3[i]));
    }
    if (tid < 64) { s2s[tid] = g_s2[tid]; b2s[tid] = g_b2o[tid]; }
    __syncthreads();

    unsigned bfrag[4][4][2];
    #pragma unroll
    for (int nt = 0; nt < 4; nt++)
        #pragma unroll
        for (int kt = 0; kt < 4; kt++) {
            unsigned addr = smem_u32(&w3h[(kt*16 + (lane & 15))*136 + n0 + nt*8]);
            ldmB(bfrag[nt][kt][0], bfrag[nt][kt][1], addr);
        }

    const int tid128 = tid & 127;
    const int kkrow  = tid128 >> 2;
    const int cg     = (tid128 & 3) * 8;

    for (int cc = 0; cc < 8; cc++) {
        const int bs = blockIdx.x*16 + cc*2 + sub;
        __syncthreads();

        {
            const __half2* src = &g_x2h[((size_t)bs*KK + kkrow)*32 + cg];
            uint4 v0 = *(const uint4*)(src);
            uint4 v1 = *(const uint4*)(src + 4);
            unsigned vv[8] = {v0.x, v0.y, v0.z, v0.w, v1.x, v1.y, v1.z, v1.w};
            #pragma unroll
            for (int j = 0; j < 8; j++) {
                __half2 hv = *(__half2*)&vv[j];
                float2 f = __half22float2(hv);
                int ch = 2*(cg + j);
                float ha = fmaxf(fmaf(f.x, s2s[ch],   b2s[ch]),   0.f);
                float hb = fmaxf(fmaf(f.y, s2s[ch+1], b2s[ch+1]), 0.f);
                *(__half2*)&h2s[sub][kkrow*72 + ch] = __floats2half2_rn(ha, hb);
            }
        }
        __syncthreads();

        unsigned af[2][4][4];
        #pragma unroll
        for (int mt = 0; mt < 2; mt++)
            #pragma unroll
            for (int kt = 0; kt < 4; kt++) {
                unsigned addr = smem_u32(&h2s[sub][(mt*16 + (lane & 15))*72
                                                   + kt*16 + (lane >> 4)*8]);
                ldmA(af[mt][kt], addr);
            }

        const size_t bs128 = (size_t)bs*128;
        const size_t bs256 = (size_t)bs*256;

        #pragma unroll
        for (int nt = 0; nt < 4; nt++) {
            float ac[2][4];
            #pragma unroll
            for (int mt = 0; mt < 2; mt++) {
                ac[mt][0] = 0.f; ac[mt][1] = 0.f; ac[mt][2] = 0.f; ac[mt][3] = 0.f;
                #pragma unroll
                for (int kt = 0; kt < 4; kt++)
                    mma16816(ac[mt], af[mt][kt], bfrag[nt][kt]);
            }
            float mx0 = fmaxf(fmaxf(ac[0][0], ac[0][2]), fmaxf(ac[1][0], ac[1][2]));
            float mx1 = fmaxf(fmaxf(ac[0][1], ac[0][3]), fmaxf(ac[1][1], ac[1][3]));
            float mn0 = fminf(fminf(ac[0][0], ac[0][2]), fminf(ac[1][0], ac[1][2]));
            float mn1 = fminf(fminf(ac[0][1], ac[0][3]), fminf(ac[1][1], ac[1][3]));
            float sm0 = (ac[0][0] + ac[0][2]) + (ac[1][0] + ac[1][2]);
            float sm1 = (ac[0][1] + ac[0][3]) + (ac[1][1] + ac[1][3]);
            float sq0 = fmaf(ac[0][0],ac[0][0], fmaf(ac[0][2],ac[0][2],
                        fmaf(ac[1][0],ac[1][0], ac[1][2]*ac[1][2])));
            float sq1 = fmaf(ac[0][1],ac[0][1], fmaf(ac[0][3],ac[0][3],
                        fmaf(ac[1][1],ac[1][1], ac[1][3]*ac[1][3])));
            #pragma unroll
            for (int o = 4; o < 32; o <<= 1) {
                mx0 = fmaxf(mx0, __shfl_xor_sync(full, mx0, o));
                mx1 = fmaxf(mx1, __shfl_xor_sync(full, mx1, o));
                mn0 = fminf(mn0, __shfl_xor_sync(full, mn0, o));
                mn1 = fminf(mn1, __shfl_xor_sync(full, mn1, o));
                sm0 += __shfl_xor_sync(full, sm0, o);
                sm1 += __shfl_xor_sync(full, sm1, o);
                sq0 += __shfl_xor_sync(full, sq0, o);
                sq1 += __shfl_xor_sync(full, sq1, o);
            }
            if (lane < 4) {
                int col = n0 + nt*8 + 2*lane;
                g_max3[bs128 + col]     = mx0;
                g_max3[bs128 + col + 1] = mx1;
                g_min3[bs128 + col]     = mn0;
                g_min3[bs128 + col + 1] = mn1;
                g_part3[bs256 + col]           = sm0;
                g_part3[bs256 + col + 1]       = sm1;
                g_part3[bs256 + 128 + col]     = sq0;
                g_part3[bs256 + 128 + col + 1] = sq1;
            }
        }
    }
}

// -------- BN3: merged two-stage reduction (last-block finalize) --------
__global__ void __launch_bounds__(256) bn3_kernel(const float* __restrict__ g,
                                                  const float* __restrict__ bv)
{
    const int tid = threadIdx.x;
    {
        float a = 0.f;
        #pragma unroll 8
        for (int p = 0; p < 128; p++)
            a += g_part3[((size_t)blockIdx.x*128 + p)*256 + tid];
        g_p3b[blockIdx.x*256 + tid] = a;
    }
    __shared__ unsigned is_last;
    __threadfence();
    if (tid == 0) is_last = (atomicAdd(&g_ctr3, 1u) == 127);
    __syncthreads();
    if (!is_last) return;

    {
        const int h = tid >> 7, c = tid & 127;
        float s = 0.f, q = 0.f;
        #pragma unroll 8
        for (int j = 0; j < 64; j++) {
            int b = h + 2*j;
            s += g_p3b[b*256 + c];
            q += g_p3b[b*256 + 128 + c];
        }
        __shared__ float ssm[256], qsm[256];
        ssm[tid] = s; qsm[tid] = q;
        __syncthreads();
        if (tid < 128) {
            float ts = ssm[tid] + ssm[tid + 128];
            float tq = qsm[tid] + qsm[tid + 128];
            float m = ts * (1.0f/524288.0f);
            float v = tq * (1.0f/524288.0f) - m*m;
            float sc = __ldg(&g[tid]) * rsqrtf(v + 1e-5f);
            g_s3[tid] = sc; g_b3o[tid] = __ldg(&bv[tid]) - m*sc;
        }
    }
    if (tid == 0) g_ctr3 = 0u;
}

// max_k relu(s*x+b) = relu(s*(s>=0? max:min) + b)
__global__ void final_kernel(float* __restrict__ out_feat)
{
    int idx = blockIdx.x * 256 + threadIdx.x;
    int c = idx & 127;
    float sc = g_s3[c], bi = g_b3o[c];
    float v = (sc >= 0.f) ? g_max3[idx] : g_min3[idx];
    out_feat[idx] = fmaxf(fmaf(v, sc, bi), 0.f);
}

// =========================================================================
extern "C" void kernel_launch(void* const* d_in, const int* in_sizes, int n_in,
                              void* d_out, int out_size)
{
    const float* xyz  = (const float*)d_in[0];
    const float* feat = (const float*)d_in[1];
    const float* W1   = (const float*)d_in[2];
    const float* g1   = (const float*)d_in[3];
    const float* b1   = (const float*)d_in[4];
    const float* W2   = (const float*)d_in[5];
    const float* g2   = (const float*)d_in[6];
    const float* b2   = (const float*)d_in[7];
    const float* W3   = (const float*)d_in[8];
    const float* g3   = (const float*)d_in[9];
    const float* b3   = (const float*)d_in[10];

    float* out   = (float*)d_out;
    float* cxyz  = out;                      // [16,1024,3]
    float* ofeat = out + (size_t)BB*SS*3;    // [16,1024,128]

    cudaFuncSetAttribute(fps_knn_kernel, cudaFuncAttributeMaxDynamicSharedMemorySize, MERGED_SMEM);

    fps_knn_kernel<<<BB + KNNB, 1024, MERGED_SMEM>>>(xyz, cxyz);
    gstats_kernel <<<GSB, 256>>>(xyz, feat, cxyz, W1, g1, b1);
    layer12_mma   <<<NB2, 256>>>(xyz, feat, cxyz, W1, W2);
    bn2_kernel    <<<32, 256>>>(g2, b2);
    layer3_mma    <<<NCTR/16, 256>>>(W3);
    bn3_kernel    <<<128, 256>>>(g3, b3);
    final_kernel  <<<(BB*SS*128)/256, 256>>>(ofeat);
}

// round 17
// speedup vs baseline: 1.2733x; 1.0024x over previous
#include <cuda_runtime.h>
#include <cuda_fp16.h>

// Problem constants
#define BB 16
#define NN 4096
#define DD 6
#define SS 1024          // NUM_CENTERS
#define KK 32
#define ROWS (BB*SS*KK)  // 524288
#define NB2  4096        // layer12 blocks (128 rows each)
#define NCTR (BB*SS)     // 16384 centers
#define GSB 512          // gstats blocks
#define KNNB 128         // knn blocks in merged kernel (8 per batch)
#define L3B  (NCTR/16)   // 1024 layer3 blocks
#define MERGED_SMEM 122880  // 120KB -> 1 block/SM, 144 blocks = single wave

// ---------------- device scratch ----------------
__device__ int   g_gidx[ROWS];                       // 2 MB
__device__ __half2 g_x2h[(size_t)ROWS*32];           // 64 MB (fp16 x2)
__device__ float g_gstat[GSB*64];
__device__ float g_part2[NB2*128];
__device__ float g_p2b[32*128];
__device__ float g_part3[(size_t)L3B*512];           // per-(block,sub) partials (2MB)
__device__ float g_p3b[128*256];
__device__ float g_max3[(size_t)NCTR*128];
__device__ float g_min3[(size_t)NCTR*128];
__device__ float g_s1[64], g_b1o[64], g_s2[64], g_b2o[64], g_s3[128], g_b3o[128];
__device__ unsigned g_ctr1, g_ctr2, g_ctr3;
__device__ volatile unsigned g_prog[BB];             // fps progress per batch

// packed f32x2 helpers
__device__ __forceinline__ unsigned long long pack2(float lo, float hi){
    unsigned long long r;
    asm("mov.b64 %0, {%1, %2};" : "=l"(r) : "f"(lo), "f"(hi));
    return r;
}
__device__ __forceinline__ void unpack2(unsigned long long v, float& lo, float& hi){
    asm("mov.b64 {%0, %1}, %2;" : "=f"(lo), "=f"(hi) : "l"(v));
}
__device__ __forceinline__ unsigned long long add2(unsigned long long a, unsigned long long b){
    unsigned long long r; asm("add.rn.f32x2 %0, %1, %2;" : "=l"(r) : "l"(a), "l"(b)); return r;
}
__device__ __forceinline__ unsigned long long mul2(unsigned long long a, unsigned long long b){
    unsigned long long r; asm("mul.rn.f32x2 %0, %1, %2;" : "=l"(r) : "l"(a), "l"(b)); return r;
}

// mma helpers
__device__ __forceinline__ unsigned smem_u32(const void* p){
    return (unsigned)__cvta_generic_to_shared(p);
}
__device__ __forceinline__ void ldmA(unsigned* r, unsigned addr){
    asm volatile("ldmatrix.sync.aligned.m8n8.x4.shared.b16 {%0,%1,%2,%3}, [%4];"
        : "=r"(r[0]),"=r"(r[1]),"=r"(r[2]),"=r"(r[3]) : "r"(addr));
}
__device__ __forceinline__ void ldmB(unsigned& b0, unsigned& b1, unsigned addr){
    asm volatile("ldmatrix.sync.aligned.m8n8.x2.trans.shared.b16 {%0,%1}, [%2];"
        : "=r"(b0),"=r"(b1) : "r"(addr));
}
__device__ __forceinline__ void mma16816(float* d, const unsigned* a, const unsigned* b){
    asm volatile("mma.sync.aligned.m16n8k16.row.col.f32.f16.f16.f32 "
        "{%0,%1,%2,%3}, {%4,%5,%6,%7}, {%8,%9}, {%0,%1,%2,%3};"
        : "+f"(d[0]),"+f"(d[1]),"+f"(d[2]),"+f"(d[3])
        : "r"(a[0]),"r"(a[1]),"r"(a[2]),"r"(a[3]), "r"(b[0]),"r"(b[1]));
}

// no-op: shifts ncu capture slot (4th launch) onto fps_knn_kernel
__global__ void dummy_kernel() {}

// =========================================================================
// Merged FPS + kNN, single wave (144 blocks, 1/SM). UNCHANGED from R15.
// =========================================================================
__global__ void __launch_bounds__(1024) fps_knn_kernel(const float* __restrict__ xyz,
                                                       float* __restrict__ out_cxyz)
{
    extern __shared__ float fsm[];
    float* sxx = fsm; float* syy = fsm + NN; float* szz = fsm + 2*NN;

    const int tid = threadIdx.x;
    const int lane = tid & 31, warp = tid >> 5;
    const unsigned full = 0xFFFFFFFFu;

    if (blockIdx.x < BB) {
        // ---------------- FPS role ----------------
        __shared__ unsigned swd[2][32];
        __shared__ unsigned swi[2][32];
        const int b = blockIdx.x;
        const float* bx = xyz + (size_t)b * NN * 3;

        for (int idx = tid; idx < NN; idx += 1024) {
            sxx[idx] = bx[idx*3+0]; syy[idx] = bx[idx*3+1]; szz[idx] = bx[idx*3+2];
        }
        __syncthreads();

        unsigned long long pxp[2], pyp[2], pzp[2];
        #pragma unroll
        for (int j = 0; j < 2; j++) {
            int p0 = tid*4 + 2*j;
            pxp[j] = pack2(sxx[p0], sxx[p0+1]);
            pyp[j] = pack2(syy[p0], syy[p0+1]);
            pzp[j] = pack2(szz[p0], szz[p0+1]);
        }
        float dmin[4];
        float c0x = sxx[0], c0y = syy[0], c0z = szz[0];
        {
            unsigned long long ncx = pack2(-c0x, -c0x);
            unsigned long long ncy = pack2(-c0y, -c0y);
            unsigned long long ncz = pack2(-c0z, -c0z);
            #pragma unroll
            for (int j = 0; j < 2; j++) {
                unsigned long long dx = add2(pxp[j], ncx);
                unsigned long long dy = add2(pyp[j], ncy);
                unsigned long long dz = add2(pzp[j], ncz);
                unsigned long long s = add2(add2(mul2(dx,dx), mul2(dy,dy)), mul2(dz,dz));
                unpack2(s, dmin[2*j], dmin[2*j+1]);
            }
        }
        if (tid == 0) {
            out_cxyz[(size_t)b*SS*3+0] = c0x;
            out_cxyz[(size_t)b*SS*3+1] = c0y;
            out_cxyz[(size_t)b*SS*3+2] = c0z;
        }

        float db; int bi_;
        {
            float v2a, v2b; int i2a, i2b;
            { bool l = dmin[0] >= dmin[1]; v2a = l ? dmin[0] : dmin[1]; i2a = l ? 0 : 1; }
            { bool l = dmin[2] >= dmin[3]; v2b = l ? dmin[2] : dmin[3]; i2b = l ? 2 : 3; }
            bool l = v2a >= v2b;
            db = l ? v2a : v2b;
            bi_ = tid*4 + (l ? i2a : i2b);
        }

        for (int t = 1; t < SS; t++) {
            unsigned dmax = __reduce_max_sync(full, __float_as_uint(db));
            unsigned cand = (__float_as_uint(db) == dmax) ? (unsigned)bi_ : 0xFFFFFFFFu;
            unsigned imin = __reduce_min_sync(full, cand);
            if (lane == 0) { swd[t&1][warp] = dmax; swi[t&1][warp] = imin; }
            __syncthreads();

            unsigned wd = swd[t&1][lane];
            unsigned wi = swi[t&1][lane];
            unsigned gmax  = __reduce_max_sync(full, wd);
            unsigned gcand = (wd == gmax) ? wi : 0xFFFFFFFFu;
            int idx = (int)__reduce_min_sync(full, gcand);

            float cx = sxx[idx], cy = syy[idx], cz = szz[idx];
            if (tid == 0) {
                out_cxyz[((size_t)b*SS + t)*3+0] = cx;
                out_cxyz[((size_t)b*SS + t)*3+1] = cy;
                out_cxyz[((size_t)b*SS + t)*3+2] = cz;
                if (((t + 1) & 15) == 0) {       // publish every 16 centers
                    __threadfence();
                    g_prog[b] = (unsigned)(t + 1);
                }
            }
            unsigned long long ncx = pack2(-cx, -cx);
            unsigned long long ncy = pack2(-cy, -cy);
            unsigned long long ncz = pack2(-cz, -cz);
            #pragma unroll
            for (int j = 0; j < 2; j++) {
                unsigned long long dx = add2(pxp[j], ncx);
                unsigned long long dy = add2(pyp[j], ncy);
                unsigned long long dz = add2(pzp[j], ncz);
                unsigned long long s = add2(add2(mul2(dx,dx), mul2(dy,dy)), mul2(dz,dz));
                float lo, hi; unpack2(s, lo, hi);
                dmin[2*j]   = fminf(dmin[2*j],   lo);
                dmin[2*j+1] = fminf(dmin[2*j+1], hi);
            }
            float v2a, v2b; int i2a, i2b;
            { bool l = dmin[0] >= dmin[1]; v2a = l ? dmin[0] : dmin[1]; i2a = l ? 0 : 1; }
            { bool l = dmin[2] >= dmin[3]; v2b = l ? dmin[2] : dmin[3]; i2b = l ? 2 : 3; }
            bool l = v2a >= v2b;
            db = l ? v2a : v2b;
            bi_ = tid*4 + (l ? i2a : i2b);
        }
    } else {
        // ---------------- kNN role ----------------
        const int kb    = blockIdx.x - BB;   // 0..127
        const int b     = kb >> 3;           // batch
        const int blkin = kb & 7;
        const float* bx = xyz + (size_t)b * NN * 3;
        const float* cxyz = out_cxyz;

        for (int j = tid; j < NN; j += 1024) {
            sxx[j] = bx[j*3+0]; syy[j] = bx[j*3+1]; szz[j] = bx[j*3+2];
        }
        __syncthreads();

        const int sbase = (warp*8 + blkin) * 4;

        if (lane == 0) {
            while (g_prog[b] < (unsigned)(sbase + 4)) __nanosleep(400);
        }
        __syncwarp();
        __threadfence();   // acquire

        float ax[4], ay[4], az[4], ra[4];
        #pragma unroll
        for (int m = 0; m < 4; m++) {
            ax[m] = __ldcg(&cxyz[((size_t)b*SS + sbase + m)*3+0]);
            ay[m] = __ldcg(&cxyz[((size_t)b*SS + sbase + m)*3+1]);
            az[m] = __ldcg(&cxyz[((size_t)b*SS + sbase + m)*3+2]);
            ra[m] = __fadd_rn(__fadd_rn(__fmul_rn(ax[m],ax[m]), __fmul_rn(ay[m],ay[m])),
                              __fmul_rn(az[m],az[m]));
        }

        unsigned hdu[4]; int hi[4]; unsigned thr_d[4]; int thr_i[4];
        {
            float bxx = sxx[lane], byy = syy[lane], bzz = szz[lane];
            float rb  = __fadd_rn(__fadd_rn(__fmul_rn(bxx,bxx), __fmul_rn(byy,byy)), __fmul_rn(bzz,bzz));
            #pragma unroll
            for (int m = 0; m < 4; m++) {
                float dot = __fadd_rn(__fadd_rn(__fmul_rn(ax[m],bxx), __fmul_rn(ay[m],byy)), __fmul_rn(az[m],bzz));
                float d = fmaxf(__fsub_rn(__fadd_rn(ra[m], rb), __fmul_rn(2.0f, dot)), 0.0f);
                hdu[m] = __float_as_uint(d);
                hi[m] = lane;
                thr_d[m] = __reduce_max_sync(full, hdu[m]);
                thr_i[m] = __reduce_max_sync(full, (hdu[m] == thr_d[m]) ? hi[m] : -1);
            }
        }

        for (int j0 = 32; j0 < NN; j0 += 32) {
            int j = j0 + lane;
            float bxx = sxx[j], byy = syy[j], bzz = szz[j];
            float rb  = __fadd_rn(__fadd_rn(__fmul_rn(bxx,bxx), __fmul_rn(byy,byy)), __fmul_rn(bzz,bzz));
            unsigned du[4];
            #pragma unroll
            for (int m = 0; m < 4; m++) {
                float dot = __fadd_rn(__fadd_rn(__fmul_rn(ax[m],bxx), __fmul_rn(ay[m],byy)), __fmul_rn(az[m],bzz));
                float d = fmaxf(__fsub_rn(__fadd_rn(ra[m], rb), __fmul_rn(2.0f, dot)), 0.0f);
                du[m] = __float_as_uint(d);
            }
            #pragma unroll
            for (int m = 0; m < 4; m++) {
                unsigned cm = __ballot_sync(full, du[m] < thr_d[m]);
                while (cm) {
                    int src = __ffs(cm) - 1;
                    cm &= cm - 1;
                    unsigned cd = __shfl_sync(full, du[m], src);
                    int ci = j0 + src;
                    if (cd < thr_d[m]) {
                        if (hdu[m] == thr_d[m] && hi[m] == thr_i[m]) { hdu[m] = cd; hi[m] = ci; }
                        thr_d[m] = __reduce_max_sync(full, hdu[m]);
                        thr_i[m] = __reduce_max_sync(full, (hdu[m] == thr_d[m]) ? hi[m] : -1);
                    }
                }
            }
        }
        #pragma unroll
        for (int m = 0; m < 4; m++)
            g_gidx[((size_t)b*SS + sbase + m)*KK + lane] = hi[m];
    }
}

// =========================================================================
// G stats + fused BN1 solve (last block via counter; deterministic).
// =========================================================================
__global__ void __launch_bounds__(256) gstats_kernel(const float* __restrict__ xyz,
                                                     const float* __restrict__ feat,
                                                     const float* __restrict__ cxyz,
                                                     const float* __restrict__ W1,
                                                     const float* __restrict__ g1v,
                                                     const float* __restrict__ b1v)
{
    const int tid = threadIdx.x;
    const int t0  = blockIdx.x * 1024 + tid;
    float s[9]; float m2[45];
    #pragma unroll
    for (int i = 0; i < 9; i++) s[i] = 0.f;
    #pragma unroll
    for (int i = 0; i < 45; i++) m2[i] = 0.f;

    #pragma unroll
    for (int m = 0; m < 4; m++) {
        int r = t0 + m*256;
        int bb = r >> 15, ssi = (r >> 5) & (SS-1);
        int gi = __ldg(&g_gidx[r]);
        const float* c = cxyz + ((size_t)bb*SS + ssi)*3;
        const float* p = xyz  + ((size_t)bb*NN + gi)*3;
        const float* f = feat + ((size_t)bb*NN + gi)*DD;
        float g[9];
        g[0] = __ldg(&p[0]) - __ldg(&c[0]);
        g[1] = __ldg(&p[1]) - __ldg(&c[1]);
        g[2] = __ldg(&p[2]) - __ldg(&c[2]);
        #pragma unroll
        for (int i = 0; i < DD; i++) g[3+i] = __ldg(&f[i]);
        #pragma unroll
        for (int i = 0; i < 9; i++) s[i] += g[i];
        int k = 0;
        #pragma unroll
        for (int i = 0; i < 9; i++)
            #pragma unroll
            for (int j = i; j < 9; j++) { m2[k] = fmaf(g[i], g[j], m2[k]); k++; }
    }
    const unsigned full = 0xFFFFFFFFu;
    #pragma unroll
    for (int q = 0; q < 9; q++)
        for (int o = 16; o > 0; o >>= 1) s[q] += __shfl_xor_sync(full, s[q], o);
    #pragma unroll
    for (int q = 0; q < 45; q++)
        for (int o = 16; o > 0; o >>= 1) m2[q] += __shfl_xor_sync(full, m2[q], o);

    __shared__ float sred[8][56];
    const int lane = tid & 31, warp = tid >> 5;
    if (lane == 0) {
        #pragma unroll
        for (int q = 0; q < 9; q++)  sred[warp][q]   = s[q];
        #pragma unroll
        for (int q = 0; q < 45; q++) sred[warp][9+q] = m2[q];
    }
    __syncthreads();
    if (tid < 54) {
        float a = 0.f;
        #pragma unroll
        for (int w = 0; w < 8; w++) a += sred[w][tid];
        g_gstat[blockIdx.x*64 + tid] = a;
    }

    __shared__ unsigned is_last;
    __threadfence();
    if (tid == 0) is_last = (atomicAdd(&g_ctr1, 1u) == GSB - 1);
    __syncthreads();
    if (!is_last) return;

    __shared__ float part[4][64];
    __shared__ double st[54];
    {
        const int c = tid & 63, r4 = tid >> 6;
        float a0 = 0.f, a1 = 0.f;
        for (int p = r4; p < GSB; p += 8) {
            a0 += g_gstat[p*64 + c];
            a1 += g_gstat[(p+4)*64 + c];
        }
        part[r4][c] = a0 + a1;
    }
    __syncthreads();
    if (tid < 54) st[tid] = (double)(part[0][tid] + part[1][tid] + part[2][tid] + part[3][tid]);
    __syncthreads();
    if (tid < 64) {
        const int t = tid;
        const double Ri = 1.0 / 524288.0;
        double w[9];
        #pragma unroll
        for (int i = 0; i < 9; i++) w[i] = (double)__ldg(&W1[i*64 + t]);
        double m1 = 0.0;
        #pragma unroll
        for (int i = 0; i < 9; i++) m1 += st[i]*Ri*w[i];
        double e2 = 0.0; int k = 0;
        #pragma unroll
        for (int i = 0; i < 9; i++)
            #pragma unroll
            for (int j = i; j < 9; j++) {
                double term = st[9+k]*Ri*w[i]*w[j];
                e2 += (i == j) ? term : 2.0*term;
                k++;
            }
        double var = e2 - m1*m1;
        double sc = (double)__ldg(&g1v[t]) / sqrt(var + 1e-5);
        g_s1[t]  = (float)sc;
        g_b1o[t] = (float)((double)__ldg(&b1v[t]) - m1*sc);
    }
    if (tid == 0) g_ctr1 = 0u;
}

// =========================================================================
// Fused layer1+2 via mma.sync fp16 (stats inline, coalesced x2 stores).
// =========================================================================
__global__ void __launch_bounds__(256) layer12_mma(const float* __restrict__ xyz,
                                                   const float* __restrict__ feat,
                                                   const float* __restrict__ cxyz,
                                                   const float* __restrict__ W1,
                                                   const float* __restrict__ W2)
{
    __shared__ __half w2h[64*72];
    __shared__ __half h1s[128*72];
    __shared__ float sg[128*10];
    __shared__ float rs[8][64], rq[8][64];

    const int tid = threadIdx.x;
    const int rowbase = blockIdx.x * 128;
    const int warp = tid >> 5, lane = tid & 31;
    const unsigned full = 0xFFFFFFFFu;

    for (int i = tid; i < 4096; i += 256) {
        int k = i >> 6, n = i & 63;
        w2h[k*72 + n] = __float2half(__ldg(&W2[i]));
    }

    if (tid < 128) {
        int r = rowbase + tid;
        int bb = r >> 15, ssi = (r >> 5) & (SS-1);
        int gi = __ldg(&g_gidx[r]);
        const float* c = cxyz + ((size_t)bb*SS + ssi)*3;
        const float* p = xyz  + ((size_t)bb*NN + gi)*3;
        const float* f = feat + ((size_t)bb*NN + gi)*DD;
        float* gg = sg + tid*10;
        gg[0] = __ldg(&p[0]) - __ldg(&c[0]);
        gg[1] = __ldg(&p[1]) - __ldg(&c[1]);
        gg[2] = __ldg(&p[2]) - __ldg(&c[2]);
        #pragma unroll
        for (int i = 0; i < DD; i++) gg[3+i] = __ldg(&f[i]);
    }
    __syncthreads();

    {
        const int c2 = tid & 31, r0 = tid >> 5;
        float wa[9], wb[9];
        #pragma unroll
        for (int i = 0; i < 9; i++) {
            wa[i] = __ldg(&W1[i*64 + 2*c2]);
            wb[i] = __ldg(&W1[i*64 + 2*c2 + 1]);
        }
        const float sa = g_s1[2*c2], sb = g_s1[2*c2+1];
        const float ba = g_b1o[2*c2], bbv = g_b1o[2*c2+1];
        #pragma unroll 4
        for (int m = 0; m < 16; m++) {
            int row = r0 + 8*m;
            const float* gg = sg + row*10;
            float xa = gg[0]*wa[0], xb = gg[0]*wb[0];
            #pragma unroll
            for (int i = 1; i < 9; i++) { float gv = gg[i]; xa = fmaf(gv, wa[i], xa); xb = fmaf(gv, wb[i], xb); }
            float ha = fmaxf(fmaf(xa, sa, ba), 0.f);
            float hb = fmaxf(fmaf(xb, sb, bbv), 0.f);
            *(__half2*)&h1s[row*72 + 2*c2] = __floats2half2_rn(ha, hb);
        }
    }
    __syncthreads();

    unsigned af[4][4];
    #pragma unroll
    for (int kt = 0; kt < 4; kt++) {
        unsigned addr = smem_u32(&h1s[(warp*16 + (lane & 15))*72 + kt*16 + (lane >> 4)*8]);
        ldmA(af[kt], addr);
    }
    __syncthreads();

    #pragma unroll
    for (int nt = 0; nt < 8; nt++) {
        unsigned bf[4][2];
        #pragma unroll
        for (int kt = 0; kt < 4; kt++) {
            unsigned addr = smem_u32(&w2h[(kt*16 + (lane & 15))*72 + nt*8]);
            ldmB(bf[kt][0], bf[kt][1], addr);
        }
        float c[4] = {0.f, 0.f, 0.f, 0.f};
        #pragma unroll
        for (int kt = 0; kt < 4; kt++) mma16816(c, af[kt], bf[kt]);

        {
            int r0s = warp*16 + (lane >> 2);
            int h2c = nt*4 + (lane & 3);
            *(__half2*)&h1s[r0s*72 + 2*h2c]     = __floats2half2_rn(c[0], c[1]);
            *(__half2*)&h1s[(r0s+8)*72 + 2*h2c] = __floats2half2_rn(c[2], c[3]);
        }
        float s0 = c[0] + c[2], s1 = c[1] + c[3];
        float q0 = fmaf(c[0], c[0], c[2]*c[2]);
        float q1 = fmaf(c[1], c[1], c[3]*c[3]);
        #pragma unroll
        for (int o = 4; o < 32; o <<= 1) {
            s0 += __shfl_xor_sync(full, s0, o);
            s1 += __shfl_xor_sync(full, s1, o);
            q0 += __shfl_xor_sync(full, q0, o);
            q1 += __shfl_xor_sync(full, q1, o);
        }
        if (lane < 4) {
            int col = nt*8 + 2*lane;
            rs[warp][col]     = s0; rs[warp][col + 1] = s1;
            rq[warp][col]     = q0; rq[warp][col + 1] = q1;
        }
    }
    __syncthreads();

    {
        char* dst = (char*)(g_x2h + (size_t)rowbase*32);
        const char* srcs = (const char*)h1s;
        #pragma unroll
        for (int j = 0; j < 4; j++) {
            int o = tid*16 + j*4096;
            int row = o >> 7, colb = o & 127;
            uint4 v = *(const uint4*)(srcs + row*144 + colb);
            *(uint4*)(dst + o) = v;
        }
    }
    if (tid < 64) {
        float a = 0.f, qq = 0.f;
        #pragma unroll
        for (int w = 0; w < 8; w++) { a += rs[w][tid]; qq += rq[w][tid]; }
        g_part2[blockIdx.x*128 + tid]      = a;
        g_part2[blockIdx.x*128 + 64 + tid] = qq;
    }
}

// -------- BN2: merged two-stage reduction (last-block finalize) --------
__global__ void __launch_bounds__(256) bn2_kernel(const float* __restrict__ g,
                                                  const float* __restrict__ bv)
{
    const int tid = threadIdx.x;
    {
        const int h = tid >> 7, c = tid & 127;
        float a = 0.f;
        #pragma unroll 8
        for (int j = 0; j < 64; j++) {
            int p = blockIdx.x*128 + h + 2*j;
            a += g_part2[p*128 + c];
        }
        __shared__ float sm[256];
        sm[tid] = a;
        __syncthreads();
        if (tid < 128) g_p2b[blockIdx.x*128 + tid] = sm[tid] + sm[tid + 128];
    }
    __shared__ unsigned is_last;
    __threadfence();
    if (tid == 0) is_last = (atomicAdd(&g_ctr2, 1u) == 31);
    __syncthreads();
    if (!is_last) return;

    if (tid < 64) {
        float s = 0.f, q = 0.f;
        #pragma unroll 8
        for (int b = 0; b < 32; b++) {
            s += g_p2b[b*128 + tid];
            q += g_p2b[b*128 + 64 + tid];
        }
        float m = s * (1.0f/524288.0f);
        float v = q * (1.0f/524288.0f) - m*m;
        float sc = __ldg(&g[tid]) * rsqrtf(v + 1e-5f);
        g_s2[tid] = sc; g_b2o[tid] = __ldg(&bv[tid]) - m*sc;
    }
    if (tid == 0) g_ctr2 = 0u;
}

// =========================================================================
// Layer 3 via mma.sync fp16 — bn3 partials per (block,sub): no writer
// collision (R16 bug fixed), 2MB instead of 16MB traffic.
// =========================================================================
__global__ void __launch_bounds__(256) layer3_mma(const float* __restrict__ W3)
{
    __shared__ __half w3h[64*136];
    __shared__ __half h2s[2][32*72];
    __shared__ float s2s[64], b2s[64];

    const int tid = threadIdx.x;
    const int warp = tid >> 5, lane = tid & 31;
    const int sub = warp >> 2;
    const int wq  = warp & 3;
    const int n0  = wq * 32;
    const unsigned full = 0xFFFFFFFFu;

    for (int i = tid; i < 8192; i += 256) {
        int k = i >> 7, n = i & 127;
        w3h[k*136 + n] = __float2half(__ldg(&W3[i]));
    }
    if (tid < 64) { s2s[tid] = g_s2[tid]; b2s[tid] = g_b2o[tid]; }
    __syncthreads();

    unsigned bfrag[4][4][2];
    #pragma unroll
    for (int nt = 0; nt < 4; nt++)
        #pragma unroll
        for (int kt = 0; kt < 4; kt++) {
            unsigned addr = smem_u32(&w3h[(kt*16 + (lane & 15))*136 + n0 + nt*8]);
            ldmB(bfrag[nt][kt][0], bfrag[nt][kt][1], addr);
        }

    const int tid128 = tid & 127;
    const int kkrow  = tid128 >> 2;
    const int cg     = (tid128 & 3) * 8;

    // per-(warp-group,sub) bn3 partial accumulators
    float aS[4][2], aQ[4][2];
    #pragma unroll
    for (int nt = 0; nt < 4; nt++) { aS[nt][0]=0.f; aS[nt][1]=0.f; aQ[nt][0]=0.f; aQ[nt][1]=0.f; }

    for (int cc = 0; cc < 8; cc++) {
        const int bs = blockIdx.x*16 + cc*2 + sub;
        __syncthreads();

        {
            const __half2* src = &g_x2h[((size_t)bs*KK + kkrow)*32 + cg];
            uint4 v0 = *(const uint4*)(src);
            uint4 v1 = *(const uint4*)(src + 4);
            unsigned vv[8] = {v0.x, v0.y, v0.z, v0.w, v1.x, v1.y, v1.z, v1.w};
            #pragma unroll
            for (int j = 0; j < 8; j++) {
                __half2 hv = *(__half2*)&vv[j];
                float2 f = __half22float2(hv);
                int ch = 2*(cg + j);
                float ha = fmaxf(fmaf(f.x, s2s[ch],   b2s[ch]),   0.f);
                float hb = fmaxf(fmaf(f.y, s2s[ch+1], b2s[ch+1]), 0.f);
                *(__half2*)&h2s[sub][kkrow*72 + ch] = __floats2half2_rn(ha, hb);
            }
        }
        __syncthreads();

        unsigned af[2][4][4];
        #pragma unroll
        for (int mt = 0; mt < 2; mt++)
            #pragma unroll
            for (int kt = 0; kt < 4; kt++) {
                unsigned addr = smem_u32(&h2s[sub][(mt*16 + (lane & 15))*72
                                                   + kt*16 + (lane >> 4)*8]);
                ldmA(af[mt][kt], addr);
            }

        const size_t bs128 = (size_t)bs*128;

        #pragma unroll
        for (int nt = 0; nt < 4; nt++) {
            float ac[2][4];
            #pragma unroll
            for (int mt = 0; mt < 2; mt++) {
                ac[mt][0] = 0.f; ac[mt][1] = 0.f; ac[mt][2] = 0.f; ac[mt][3] = 0.f;
                #pragma unroll
                for (int kt = 0; kt < 4; kt++)
                    mma16816(ac[mt], af[mt][kt], bfrag[nt][kt]);
            }
            float mx0 = fmaxf(fmaxf(ac[0][0], ac[0][2]), fmaxf(ac[1][0], ac[1][2]));
            float mx1 = fmaxf(fmaxf(ac[0][1], ac[0][3]), fmaxf(ac[1][1], ac[1][3]));
            float mn0 = fminf(fminf(ac[0][0], ac[0][2]), fminf(ac[1][0], ac[1][2]));
            float mn1 = fminf(fminf(ac[0][1], ac[0][3]), fminf(ac[1][1], ac[1][3]));
            float sm0 = (ac[0][0] + ac[0][2]) + (ac[1][0] + ac[1][2]);
            float sm1 = (ac[0][1] + ac[0][3]) + (ac[1][1] + ac[1][3]);
            float sq0 = fmaf(ac[0][0],ac[0][0], fmaf(ac[0][2],ac[0][2],
                        fmaf(ac[1][0],ac[1][0], ac[1][2]*ac[1][2])));
            float sq1 = fmaf(ac[0][1],ac[0][1], fmaf(ac[0][3],ac[0][3],
                        fmaf(ac[1][1],ac[1][1], ac[1][3]*ac[1][3])));
            #pragma unroll
            for (int o = 4; o < 32; o <<= 1) {
                mx0 = fmaxf(mx0, __shfl_xor_sync(full, mx0, o));
                mx1 = fmaxf(mx1, __shfl_xor_sync(full, mx1, o));
                mn0 = fminf(mn0, __shfl_xor_sync(full, mn0, o));
                mn1 = fminf(mn1, __shfl_xor_sync(full, mn1, o));
                sm0 += __shfl_xor_sync(full, sm0, o);
                sm1 += __shfl_xor_sync(full, sm1, o);
                sq0 += __shfl_xor_sync(full, sq0, o);
                sq1 += __shfl_xor_sync(full, sq1, o);
            }
            aS[nt][0] += sm0; aS[nt][1] += sm1;
            aQ[nt][0] += sq0; aQ[nt][1] += sq1;
            if (lane < 4) {
                int col = n0 + nt*8 + 2*lane;
                g_max3[bs128 + col]     = mx0;
                g_max3[bs128 + col + 1] = mx1;
                g_min3[bs128 + col]     = mn0;
                g_min3[bs128 + col + 1] = mn1;
            }
        }
    }
    // one partial row per (block, sub): no collision between sub groups
    if (lane < 4) {
        const size_t pb = ((size_t)blockIdx.x*2 + sub)*256;
        #pragma unroll
        for (int nt = 0; nt < 4; nt++) {
            int col = n0 + nt*8 + 2*lane;
            g_part3[pb + col]           = aS[nt][0];
            g_part3[pb + col + 1]       = aS[nt][1];
            g_part3[pb + 128 + col]     = aQ[nt][0];
            g_part3[pb + 128 + col + 1] = aQ[nt][1];
        }
    }
}

// -------- BN3: merged two-stage reduction over 2048 partial rows --------
__global__ void __launch_bounds__(256) bn3_kernel(const float* __restrict__ g,
                                                  const float* __restrict__ bv)
{
    const int tid = threadIdx.x;
    {
        float a = 0.f;
        #pragma unroll
        for (int p = 0; p < 16; p++)
            a += g_part3[((size_t)blockIdx.x*16 + p)*256 + tid];
        g_p3b[blockIdx.x*256 + tid] = a;
    }
    __shared__ unsigned is_last;
    __threadfence();
    if (tid == 0) is_last = (atomicAdd(&g_ctr3, 1u) == 127);
    __syncthreads();
    if (!is_last) return;

    {
        const int h = tid >> 7, c = tid & 127;
        float s = 0.f, q = 0.f;
        #pragma unroll 8
        for (int j = 0; j < 64; j++) {
            int b = h + 2*j;
            s += g_p3b[b*256 + c];
            q += g_p3b[b*256 + 128 + c];
        }
        __shared__ float ssm[256], qsm[256];
        ssm[tid] = s; qsm[tid] = q;
        __syncthreads();
        if (tid < 128) {
            float ts = ssm[tid] + ssm[tid + 128];
            float tq = qsm[tid] + qsm[tid + 128];
            float m = ts * (1.0f/524288.0f);
            float v = tq * (1.0f/524288.0f) - m*m;
            float sc = __ldg(&g[tid]) * rsqrtf(v + 1e-5f);
            g_s3[tid] = sc; g_b3o[tid] = __ldg(&bv[tid]) - m*sc;
        }
    }
    if (tid == 0) g_ctr3 = 0u;
}

// max_k relu(s*x+b) = relu(s*(s>=0? max:min) + b)
__global__ void final_kernel(float* __restrict__ out_feat)
{
    int idx = blockIdx.x * 256 + threadIdx.x;
    int c = idx & 127;
    float sc = g_s3[c], bi = g_b3o[c];
    float v = (sc >= 0.f) ? g_max3[idx] : g_min3[idx];
    out_feat[idx] = fmaxf(fmaf(v, sc, bi), 0.f);
}

// =========================================================================
extern "C" void kernel_launch(void* const* d_in, const int* in_sizes, int n_in,
                              void* d_out, int out_size)
{
    const float* xyz  = (const float*)d_in[0];
    const float* feat = (const float*)d_in[1];
    const float* W1   = (const float*)d_in[2];
    const float* g1   = (const float*)d_in[3];
    const float* b1   = (const float*)d_in[4];
    const float* W2   = (const float*)d_in[5];
    const float* g2   = (const float*)d_in[6];
    const float* b2   = (const float*)d_in[7];
    const float* W3   = (const float*)d_in[8];
    const float* g3   = (const float*)d_in[9];
    const float* b3   = (const float*)d_in[10];

    float* out   = (float*)d_out;
    float* cxyz  = out;                      // [16,1024,3]
    float* ofeat = out + (size_t)BB*SS*3;    // [16,1024,128]

    cudaFuncSetAttribute(fps_knn_kernel, cudaFuncAttributeMaxDynamicSharedMemorySize, MERGED_SMEM);

    // 3 dummies: ncu capture slot (4th launch) -> fps_knn_kernel
    dummy_kernel  <<<1, 32>>>();
    dummy_kernel  <<<1, 32>>>();
    dummy_kernel  <<<1, 32>>>();

    fps_knn_kernel<<<BB + KNNB, 1024, MERGED_SMEM>>>(xyz, cxyz);
    gstats_kernel <<<GSB, 256>>>(xyz, feat, cxyz, W1, g1, b1);
    layer12_mma   <<<NB2, 256>>>(xyz, feat, cxyz, W1, W2);
    bn2_kernel    <<<32, 256>>>(g2, b2);
    layer3_mma    <<<L3B, 256>>>(W3);
    bn3_kernel    <<<128, 256>>>(g3, b3);
    final_kernel  <<<(BB*SS*128)/256, 256>>>(ofeat);
}